// round 1
// baseline (speedup 1.0000x reference)
#include <cuda_runtime.h>
#include <math.h>

// Problem constants
#define TOKS   4096   // B*N
#define DDIM   512
#define SSLOTS 1024
#define QDIM   320
#define KSEL   32
#define NHEAD  8
#define DHEAD  64

// ---------------- scratch (device globals; no allocation allowed) ----------
__device__ float g_q[TOKS * DDIM];
__device__ float g_keysN[SSLOTS * DDIM];
__device__ float g_valsN[SSLOTS * DDIM];
__device__ float g_Kp[SSLOTS * DDIM];
__device__ float g_Vp[SSLOTS * DDIM];
__device__ float g_qh[TOKS * DDIM];
__device__ float g_scores[TOKS * SSLOTS];
__device__ int   g_topidx[TOKS * KSEL];
__device__ float g_ctx[TOKS * DDIM];
__device__ float g_ctxo[TOKS * DDIM];
__device__ float g_normed[TOKS * DDIM];

// ---------------- GEMM NT: C[M,N] = A[M,K] * B[N,K]^T (+optional bias) -----
// Requires: M%64==0, N%64==0, K%16==0. All our shapes satisfy this.
#define GBM 64
#define GBN 64
#define GBK 16

__global__ __launch_bounds__(256)
void gemm_nt(const float* __restrict__ A, const float* __restrict__ B,
             float* __restrict__ C, int M, int N, int K,
             const float* __restrict__ bias)
{
    // transposed smem tiles so compute reads are float4 along M/N
    __shared__ float Ast[GBK][GBM + 4];
    __shared__ float Bst[GBK][GBN + 4];

    const int tid  = threadIdx.x;           // 256 threads
    const int brow = blockIdx.y * GBM;
    const int bcol = blockIdx.x * GBN;
    const int tx   = tid & 15;               // 0..15 -> 4 cols each
    const int ty   = tid >> 4;               // 0..15 -> 4 rows each
    const int lrow = tid >> 2;               // 0..63 tile row to load
    const int lc4  = tid & 3;                // which float4 of the 16-wide K slab

    const float* Aptr = A + (size_t)(brow + lrow) * K + lc4 * 4;
    const float* Bptr = B + (size_t)(bcol + lrow) * K + lc4 * 4;

    float acc[4][4];
#pragma unroll
    for (int i = 0; i < 4; i++)
#pragma unroll
        for (int j = 0; j < 4; j++) acc[i][j] = 0.f;

    for (int k0 = 0; k0 < K; k0 += GBK) {
        float4 a4 = *(const float4*)(Aptr + k0);
        float4 b4 = *(const float4*)(Bptr + k0);
        Ast[lc4 * 4 + 0][lrow] = a4.x;
        Ast[lc4 * 4 + 1][lrow] = a4.y;
        Ast[lc4 * 4 + 2][lrow] = a4.z;
        Ast[lc4 * 4 + 3][lrow] = a4.w;
        Bst[lc4 * 4 + 0][lrow] = b4.x;
        Bst[lc4 * 4 + 1][lrow] = b4.y;
        Bst[lc4 * 4 + 2][lrow] = b4.z;
        Bst[lc4 * 4 + 3][lrow] = b4.w;
        __syncthreads();
#pragma unroll
        for (int kk = 0; kk < GBK; kk++) {
            float4 av = *(const float4*)&Ast[kk][ty * 4];
            float4 bv = *(const float4*)&Bst[kk][tx * 4];
            float a[4] = {av.x, av.y, av.z, av.w};
            float b[4] = {bv.x, bv.y, bv.z, bv.w};
#pragma unroll
            for (int i = 0; i < 4; i++)
#pragma unroll
                for (int j = 0; j < 4; j++)
                    acc[i][j] = fmaf(a[i], b[j], acc[i][j]);
        }
        __syncthreads();
    }

#pragma unroll
    for (int i = 0; i < 4; i++) {
        int row = brow + ty * 4 + i;
        int col = bcol + tx * 4;
        float4 o = make_float4(acc[i][0], acc[i][1], acc[i][2], acc[i][3]);
        if (bias) {
            o.x += bias[col + 0];
            o.y += bias[col + 1];
            o.z += bias[col + 2];
            o.w += bias[col + 3];
        }
        *(float4*)(C + (size_t)row * N + col) = o;
    }
}

// ---------------- L2 normalize memory slots (keys & values) ----------------
__global__ __launch_bounds__(256)
void l2norm_kernel(const float* __restrict__ keys, const float* __restrict__ vals)
{
    __shared__ float sbuf[8];
    const int row = blockIdx.x;
    const float* src = (blockIdx.y == 0) ? keys : vals;
    float* dst = (blockIdx.y == 0) ? g_keysN : g_valsN;
    const int t = threadIdx.x;

    float2 v = *(const float2*)(src + (size_t)row * DDIM + t * 2);
    float ss = v.x * v.x + v.y * v.y;
#pragma unroll
    for (int off = 16; off; off >>= 1) ss += __shfl_xor_sync(0xffffffffu, ss, off);
    if ((t & 31) == 0) sbuf[t >> 5] = ss;
    __syncthreads();
    float tot = 0.f;
#pragma unroll
    for (int w = 0; w < 8; w++) tot += sbuf[w];
    float inv = 1.0f / sqrtf(tot + 1e-12f);
    float2 o = make_float2(v.x * inv, v.y * inv);
    *(float2*)(dst + (size_t)row * DDIM + t * 2) = o;
}

// ---------------- top-32 of 1024 per row (iterative block argmax) ----------
__global__ __launch_bounds__(256)
void topk_kernel(const float* __restrict__ scores, int* __restrict__ topidx)
{
    __shared__ float s_val[SSLOTS];
    __shared__ float r_val[8];
    __shared__ int   r_idx[8];
    const int row = blockIdx.x;
    const int t = threadIdx.x;

    for (int i = t; i < SSLOTS; i += 256)
        s_val[i] = scores[(size_t)row * SSLOTS + i];
    __syncthreads();

    for (int sel = 0; sel < KSEL; sel++) {
        float best = -INFINITY;
        int bi = SSLOTS;  // sentinel larger than any valid idx
        for (int i = t; i < SSLOTS; i += 256) {
            float v = s_val[i];
            if (v > best || (v == best && i < bi)) { best = v; bi = i; }
        }
#pragma unroll
        for (int off = 16; off; off >>= 1) {
            float ov = __shfl_xor_sync(0xffffffffu, best, off);
            int   oi = __shfl_xor_sync(0xffffffffu, bi, off);
            if (ov > best || (ov == best && oi < bi)) { best = ov; bi = oi; }
        }
        if ((t & 31) == 0) { r_val[t >> 5] = best; r_idx[t >> 5] = bi; }
        __syncthreads();
        if (t == 0) {
            float bb = r_val[0];
            int bbi = r_idx[0];
#pragma unroll
            for (int w = 1; w < 8; w++) {
                if (r_val[w] > bb || (r_val[w] == bb && r_idx[w] < bbi)) {
                    bb = r_val[w]; bbi = r_idx[w];
                }
            }
            topidx[(size_t)row * KSEL + sel] = bbi;
            s_val[bbi] = -INFINITY;
        }
        __syncthreads();
    }
}

// ---------------- gathered multi-head attention over top-K slots -----------
// One block per token. att[h,k] = qh[h,:]. Kp[idx_k, h,:] / 8 ; softmax over k
// ctx[h*64+d] = sum_k w[h,k] * Vp[idx_k, h*64+d]
__global__ __launch_bounds__(256)
void attn_kernel(const float* __restrict__ qh, const int* __restrict__ topidx,
                 float* __restrict__ ctx)
{
    __shared__ int   s_idx[KSEL];
    __shared__ float s_q[DDIM];
    __shared__ float s_w[NHEAD][KSEL];

    const int bn = blockIdx.x;
    const int t = threadIdx.x;

    if (t < KSEL) s_idx[t] = topidx[(size_t)bn * KSEL + t];
    s_q[t]       = qh[(size_t)bn * DDIM + t];
    s_q[t + 256] = qh[(size_t)bn * DDIM + t + 256];
    __syncthreads();

    const int h = t >> 5;   // one warp per head
    const int k = t & 31;   // lane = slot within top-K
    const float* kp = g_Kp + (size_t)s_idx[k] * DDIM + h * DHEAD;
    const float* qr = &s_q[h * DHEAD];
    float dot = 0.f;
#pragma unroll
    for (int j = 0; j < DHEAD; j += 4) {
        float4 kv = *(const float4*)(kp + j);
        dot += qr[j] * kv.x + qr[j + 1] * kv.y + qr[j + 2] * kv.z + qr[j + 3] * kv.w;
    }
    dot *= 0.125f;  // 1/sqrt(64)

    float m = dot;
#pragma unroll
    for (int off = 16; off; off >>= 1) m = fmaxf(m, __shfl_xor_sync(0xffffffffu, m, off));
    float e = expf(dot - m);
    float s = e;
#pragma unroll
    for (int off = 16; off; off >>= 1) s += __shfl_xor_sync(0xffffffffu, s, off);
    s_w[h][k] = e / s;
    __syncthreads();

#pragma unroll
    for (int rep = 0; rep < 2; rep++) {
        int d = t + rep * 256;
        int hh = d >> 6;
        float acc = 0.f;
#pragma unroll 8
        for (int kk = 0; kk < KSEL; kk++)
            acc += s_w[hh][kk] * g_Vp[(size_t)s_idx[kk] * DDIM + d];
        ctx[(size_t)bn * DDIM + d] = acc;
    }
}

// ---------------- LayerNorm over D=512 -------------------------------------
__global__ __launch_bounds__(256)
void ln_kernel(const float* __restrict__ x, const float* __restrict__ g,
               const float* __restrict__ b, float* __restrict__ y)
{
    __shared__ float sbuf[8];
    __shared__ float sbuf2[8];
    const int row = blockIdx.x;
    const int t = threadIdx.x;

    float2 v = *(const float2*)(x + (size_t)row * DDIM + t * 2);
    float s = v.x + v.y;
#pragma unroll
    for (int off = 16; off; off >>= 1) s += __shfl_xor_sync(0xffffffffu, s, off);
    if ((t & 31) == 0) sbuf[t >> 5] = s;
    __syncthreads();
    float tot = 0.f;
#pragma unroll
    for (int w = 0; w < 8; w++) tot += sbuf[w];
    float mu = tot * (1.0f / DDIM);

    float dx = v.x - mu, dy = v.y - mu;
    float ss = dx * dx + dy * dy;
#pragma unroll
    for (int off = 16; off; off >>= 1) ss += __shfl_xor_sync(0xffffffffu, ss, off);
    if ((t & 31) == 0) sbuf2[t >> 5] = ss;
    __syncthreads();
    float vs = 0.f;
#pragma unroll
    for (int w = 0; w < 8; w++) vs += sbuf2[w];
    float rstd = 1.0f / sqrtf(vs * (1.0f / DDIM) + 1e-5f);

    float2 o;
    o.x = dx * rstd * g[t * 2 + 0] + b[t * 2 + 0];
    o.y = dy * rstd * g[t * 2 + 1] + b[t * 2 + 1];
    *(float2*)(y + (size_t)row * DDIM + t * 2) = o;
}

// ---------------- launch ----------------------------------------------------
extern "C" void kernel_launch(void* const* d_in, const int* in_sizes, int n_in,
                              void* d_out, int out_size)
{
    const float* query = (const float*)d_in[0];   // [4,1024,320]
    const float* Wqp   = (const float*)d_in[1];   // [512,320]
    const float* mkeys = (const float*)d_in[2];   // [1024,512]
    const float* mvals = (const float*)d_in[3];   // [1024,512]
    const float* Wq    = (const float*)d_in[4];   // [512,512]
    const float* Wk    = (const float*)d_in[5];
    const float* Wv    = (const float*)d_in[6];
    const float* Wo    = (const float*)d_in[7];
    const float* ln_g  = (const float*)d_in[8];   // [512]
    const float* ln_b  = (const float*)d_in[9];   // [512]
    const float* Wout  = (const float*)d_in[10];  // [320,512]
    const float* bout  = (const float*)d_in[11];  // [320]
    float* out = (float*)d_out;                   // [4,1024,320]

    float *q, *keysN, *valsN, *Kp, *Vp, *qh, *scores, *ctx, *ctxo, *normed;
    int* topidx;
    cudaGetSymbolAddress((void**)&q,      g_q);
    cudaGetSymbolAddress((void**)&keysN,  g_keysN);
    cudaGetSymbolAddress((void**)&valsN,  g_valsN);
    cudaGetSymbolAddress((void**)&Kp,     g_Kp);
    cudaGetSymbolAddress((void**)&Vp,     g_Vp);
    cudaGetSymbolAddress((void**)&qh,     g_qh);
    cudaGetSymbolAddress((void**)&scores, g_scores);
    cudaGetSymbolAddress((void**)&topidx, g_topidx);
    cudaGetSymbolAddress((void**)&ctx,    g_ctx);
    cudaGetSymbolAddress((void**)&ctxo,   g_ctxo);
    cudaGetSymbolAddress((void**)&normed, g_normed);

    // 1) normalize slot tables
    l2norm_kernel<<<dim3(SSLOTS, 2), 256>>>(mkeys, mvals);

    // 2) project slot tables ONCE (replaces per-token gathered projection)
    gemm_nt<<<dim3(DDIM / GBN, SSLOTS / GBM), 256>>>(keysN, Wk, Kp, SSLOTS, DDIM, DDIM, nullptr);
    gemm_nt<<<dim3(DDIM / GBN, SSLOTS / GBM), 256>>>(valsN, Wv, Vp, SSLOTS, DDIM, DDIM, nullptr);

    // 3) q = query @ Wqp^T   [4096,512]
    gemm_nt<<<dim3(DDIM / GBN, TOKS / GBM), 256>>>(query, Wqp, q, TOKS, DDIM, QDIM, nullptr);

    // 4) qh = q @ Wq^T       [4096,512]
    gemm_nt<<<dim3(DDIM / GBN, TOKS / GBM), 256>>>(q, Wq, qh, TOKS, DDIM, DDIM, nullptr);

    // 5) scores = q @ keysN^T  [4096,1024]
    gemm_nt<<<dim3(SSLOTS / GBN, TOKS / GBM), 256>>>(q, keysN, scores, TOKS, SSLOTS, DDIM, nullptr);

    // 6) top-32 per token
    topk_kernel<<<TOKS, 256>>>(scores, topidx);

    // 7) gathered multi-head attention -> ctx [4096,512]
    attn_kernel<<<TOKS, 256>>>(qh, topidx, ctx);

    // 8) ctxo = ctx @ Wo^T
    gemm_nt<<<dim3(DDIM / GBN, TOKS / GBM), 256>>>(ctx, Wo, ctxo, TOKS, DDIM, DDIM, nullptr);

    // 9) LayerNorm
    ln_kernel<<<TOKS, 256>>>(ctxo, ln_g, ln_b, normed);

    // 10) out = normed @ Wout^T + bout  [4096,320]
    gemm_nt<<<dim3(QDIM / GBN, TOKS / GBM), 256>>>(normed, Wout, out, TOKS, QDIM, DDIM, bout);
}

// round 2
// speedup vs baseline: 1.0619x; 1.0619x over previous
#include <cuda_runtime.h>
#include <math.h>

// Problem constants
#define TOKS   4096   // B*N
#define DDIM   512
#define SSLOTS 1024
#define QDIM   320
#define KSEL   32
#define NHEAD  8
#define DHEAD  64

// ---------------- scratch (device globals; no allocation allowed) ----------
__device__ float g_q[TOKS * DDIM];
__device__ float g_keysN[SSLOTS * DDIM];
__device__ float g_valsN[SSLOTS * DDIM];
__device__ float g_Kp[SSLOTS * DDIM];
__device__ float g_Vp[SSLOTS * DDIM];
__device__ float g_qh[TOKS * DDIM];
__device__ float g_scores[TOKS * SSLOTS];
__device__ int   g_topidx[TOKS * KSEL];
__device__ float g_ctx[TOKS * DDIM];
__device__ float g_ctxo[TOKS * DDIM];
__device__ float g_normed[TOKS * DDIM];

// ============================================================================
// GEMM NT: C[M,N] = A[M,K] * B[N,K]^T (+optional bias)
// 8x8 register micro-tiles, BK=16, double-buffered smem, register prefetch.
// Requires M % BM == 0, N % BN == 0, K % 16 == 0.
// ============================================================================
template<int BM, int BN>
__device__ __forceinline__ void gemm_body(
    const float* __restrict__ A, const float* __restrict__ B,
    float* __restrict__ C, int M, int N, int K,
    const float* __restrict__ bias)
{
    constexpr int BK  = 16;
    constexpr int NT  = (BM / 8) * (BN / 8);
    constexpr int AF4 = BM * BK / 4 / NT;   // float4 loads per thread for A
    constexpr int BF4 = BN * BK / 4 / NT;
    constexpr int PAD = 4;

    __shared__ float As[2][BK][BM + PAD];
    __shared__ float Bs[2][BK][BN + PAD];

    const int tid  = threadIdx.x;
    const int tx   = tid % (BN / 8);
    const int ty   = tid / (BN / 8);
    const int brow = blockIdx.y * BM;
    const int bcol = blockIdx.x * BN;

    float4 pa[AF4], pb[BF4];

    auto loadA = [&](int k0) {
#pragma unroll
        for (int i = 0; i < AF4; i++) {
            int slot = tid + i * NT;
            int m = slot >> 2, kq = slot & 3;
            pa[i] = *(const float4*)(A + (size_t)(brow + m) * K + k0 + kq * 4);
        }
    };
    auto loadB = [&](int k0) {
#pragma unroll
        for (int i = 0; i < BF4; i++) {
            int slot = tid + i * NT;
            int n = slot >> 2, kq = slot & 3;
            pb[i] = *(const float4*)(B + (size_t)(bcol + n) * K + k0 + kq * 4);
        }
    };
    auto storeA = [&](int buf) {
#pragma unroll
        for (int i = 0; i < AF4; i++) {
            int slot = tid + i * NT;
            int m = slot >> 2, kq = slot & 3;
            As[buf][kq * 4 + 0][m] = pa[i].x;
            As[buf][kq * 4 + 1][m] = pa[i].y;
            As[buf][kq * 4 + 2][m] = pa[i].z;
            As[buf][kq * 4 + 3][m] = pa[i].w;
        }
    };
    auto storeB = [&](int buf) {
#pragma unroll
        for (int i = 0; i < BF4; i++) {
            int slot = tid + i * NT;
            int n = slot >> 2, kq = slot & 3;
            Bs[buf][kq * 4 + 0][n] = pb[i].x;
            Bs[buf][kq * 4 + 1][n] = pb[i].y;
            Bs[buf][kq * 4 + 2][n] = pb[i].z;
            Bs[buf][kq * 4 + 3][n] = pb[i].w;
        }
    };

    float acc[8][8];
#pragma unroll
    for (int i = 0; i < 8; i++)
#pragma unroll
        for (int j = 0; j < 8; j++) acc[i][j] = 0.f;

    const int ntiles = K / BK;
    loadA(0); loadB(0);
    storeA(0); storeB(0);
    __syncthreads();

    for (int t = 0; t < ntiles; t++) {
        const int cur = t & 1;
        const bool more = (t + 1 < ntiles);
        if (more) { loadA((t + 1) * BK); loadB((t + 1) * BK); }

#pragma unroll
        for (int kk = 0; kk < BK; kk++) {
            float a[8], b[8];
            *(float4*)(a)     = *(const float4*)&As[cur][kk][ty * 8];
            *(float4*)(a + 4) = *(const float4*)&As[cur][kk][ty * 8 + 4];
            *(float4*)(b)     = *(const float4*)&Bs[cur][kk][tx * 8];
            *(float4*)(b + 4) = *(const float4*)&Bs[cur][kk][tx * 8 + 4];
#pragma unroll
            for (int i = 0; i < 8; i++)
#pragma unroll
                for (int j = 0; j < 8; j++)
                    acc[i][j] = fmaf(a[i], b[j], acc[i][j]);
        }
        if (more) {
            storeA(cur ^ 1); storeB(cur ^ 1);
        }
        __syncthreads();
    }

#pragma unroll
    for (int i = 0; i < 8; i++) {
        const int row = brow + ty * 8 + i;
        const int col = bcol + tx * 8;
        float4 o0 = make_float4(acc[i][0], acc[i][1], acc[i][2], acc[i][3]);
        float4 o1 = make_float4(acc[i][4], acc[i][5], acc[i][6], acc[i][7]);
        if (bias) {
            o0.x += bias[col + 0]; o0.y += bias[col + 1];
            o0.z += bias[col + 2]; o0.w += bias[col + 3];
            o1.x += bias[col + 4]; o1.y += bias[col + 5];
            o1.z += bias[col + 6]; o1.w += bias[col + 7];
        }
        *(float4*)(C + (size_t)row * N + col)     = o0;
        *(float4*)(C + (size_t)row * N + col + 4) = o1;
    }
}

template<int BM, int BN>
__global__ void __launch_bounds__((BM / 8) * (BN / 8))
gemm_t(const float* __restrict__ A, const float* __restrict__ B,
       float* __restrict__ C, int M, int N, int K,
       const float* __restrict__ bias)
{
    gemm_body<BM, BN>(A, B, C, M, N, K, bias);
}

// Dual GEMM: blockIdx.z selects between two (A,B,C) triples of equal shape.
template<int BM, int BN>
__global__ void __launch_bounds__((BM / 8) * (BN / 8))
gemm_dual_t(const float* __restrict__ A0, const float* __restrict__ B0, float* __restrict__ C0,
            const float* __restrict__ A1, const float* __restrict__ B1, float* __restrict__ C1,
            int M, int N, int K)
{
    const float* A = blockIdx.z ? A1 : A0;
    const float* B = blockIdx.z ? B1 : B0;
    float*       C = blockIdx.z ? C1 : C0;
    gemm_body<BM, BN>(A, B, C, M, N, K, nullptr);
}

// ---------------- L2 normalize memory slots (keys & values) ----------------
__global__ __launch_bounds__(256)
void l2norm_kernel(const float* __restrict__ keys, const float* __restrict__ vals)
{
    __shared__ float sbuf[8];
    const int row = blockIdx.x;
    const float* src = (blockIdx.y == 0) ? keys : vals;
    float* dst = (blockIdx.y == 0) ? g_keysN : g_valsN;
    const int t = threadIdx.x;

    float2 v = *(const float2*)(src + (size_t)row * DDIM + t * 2);
    float ss = v.x * v.x + v.y * v.y;
#pragma unroll
    for (int off = 16; off; off >>= 1) ss += __shfl_xor_sync(0xffffffffu, ss, off);
    if ((t & 31) == 0) sbuf[t >> 5] = ss;
    __syncthreads();
    float tot = 0.f;
#pragma unroll
    for (int w = 0; w < 8; w++) tot += sbuf[w];
    float inv = 1.0f / sqrtf(tot + 1e-12f);
    float2 o = make_float2(v.x * inv, v.y * inv);
    *(float2*)(dst + (size_t)row * DDIM + t * 2) = o;
}

// ---------------- top-32 of 1024 per row (iterative block argmax) ----------
__global__ __launch_bounds__(256)
void topk_kernel(const float* __restrict__ scores, int* __restrict__ topidx)
{
    __shared__ float s_val[SSLOTS];
    __shared__ float r_val[8];
    __shared__ int   r_idx[8];
    const int row = blockIdx.x;
    const int t = threadIdx.x;

    for (int i = t; i < SSLOTS; i += 256)
        s_val[i] = scores[(size_t)row * SSLOTS + i];
    __syncthreads();

    for (int sel = 0; sel < KSEL; sel++) {
        float best = -INFINITY;
        int bi = SSLOTS;  // sentinel larger than any valid idx
        for (int i = t; i < SSLOTS; i += 256) {
            float v = s_val[i];
            if (v > best || (v == best && i < bi)) { best = v; bi = i; }
        }
#pragma unroll
        for (int off = 16; off; off >>= 1) {
            float ov = __shfl_xor_sync(0xffffffffu, best, off);
            int   oi = __shfl_xor_sync(0xffffffffu, bi, off);
            if (ov > best || (ov == best && oi < bi)) { best = ov; bi = oi; }
        }
        if ((t & 31) == 0) { r_val[t >> 5] = best; r_idx[t >> 5] = bi; }
        __syncthreads();
        if (t == 0) {
            float bb = r_val[0];
            int bbi = r_idx[0];
#pragma unroll
            for (int w = 1; w < 8; w++) {
                if (r_val[w] > bb || (r_val[w] == bb && r_idx[w] < bbi)) {
                    bb = r_val[w]; bbi = r_idx[w];
                }
            }
            topidx[(size_t)row * KSEL + sel] = bbi;
            s_val[bbi] = -INFINITY;
        }
        __syncthreads();
    }
}

// ---------------- gathered multi-head attention over top-K slots -----------
__global__ __launch_bounds__(256)
void attn_kernel(const float* __restrict__ qh, const int* __restrict__ topidx,
                 float* __restrict__ ctx)
{
    __shared__ int   s_idx[KSEL];
    __shared__ float s_q[DDIM];
    __shared__ float s_w[NHEAD][KSEL];

    const int bn = blockIdx.x;
    const int t = threadIdx.x;

    if (t < KSEL) s_idx[t] = topidx[(size_t)bn * KSEL + t];
    s_q[t]       = qh[(size_t)bn * DDIM + t];
    s_q[t + 256] = qh[(size_t)bn * DDIM + t + 256];
    __syncthreads();

    const int h = t >> 5;   // one warp per head
    const int k = t & 31;   // lane = slot within top-K
    const float* kp = g_Kp + (size_t)s_idx[k] * DDIM + h * DHEAD;
    const float* qr = &s_q[h * DHEAD];
    float dot = 0.f;
#pragma unroll
    for (int j = 0; j < DHEAD; j += 4) {
        float4 kv = *(const float4*)(kp + j);
        dot += qr[j] * kv.x + qr[j + 1] * kv.y + qr[j + 2] * kv.z + qr[j + 3] * kv.w;
    }
    dot *= 0.125f;  // 1/sqrt(64)

    float m = dot;
#pragma unroll
    for (int off = 16; off; off >>= 1) m = fmaxf(m, __shfl_xor_sync(0xffffffffu, m, off));
    float e = expf(dot - m);
    float s = e;
#pragma unroll
    for (int off = 16; off; off >>= 1) s += __shfl_xor_sync(0xffffffffu, s, off);
    s_w[h][k] = e / s;
    __syncthreads();

#pragma unroll
    for (int rep = 0; rep < 2; rep++) {
        int d = t + rep * 256;
        int hh = d >> 6;
        float acc = 0.f;
#pragma unroll 8
        for (int kk = 0; kk < KSEL; kk++)
            acc += s_w[hh][kk] * g_Vp[(size_t)s_idx[kk] * DDIM + d];
        ctx[(size_t)bn * DDIM + d] = acc;
    }
}

// ---------------- LayerNorm over D=512 -------------------------------------
__global__ __launch_bounds__(256)
void ln_kernel(const float* __restrict__ x, const float* __restrict__ g,
               const float* __restrict__ b, float* __restrict__ y)
{
    __shared__ float sbuf[8];
    __shared__ float sbuf2[8];
    const int row = blockIdx.x;
    const int t = threadIdx.x;

    float2 v = *(const float2*)(x + (size_t)row * DDIM + t * 2);
    float s = v.x + v.y;
#pragma unroll
    for (int off = 16; off; off >>= 1) s += __shfl_xor_sync(0xffffffffu, s, off);
    if ((t & 31) == 0) sbuf[t >> 5] = s;
    __syncthreads();
    float tot = 0.f;
#pragma unroll
    for (int w = 0; w < 8; w++) tot += sbuf[w];
    float mu = tot * (1.0f / DDIM);

    float dx = v.x - mu, dy = v.y - mu;
    float ss = dx * dx + dy * dy;
#pragma unroll
    for (int off = 16; off; off >>= 1) ss += __shfl_xor_sync(0xffffffffu, ss, off);
    if ((t & 31) == 0) sbuf2[t >> 5] = ss;
    __syncthreads();
    float vs = 0.f;
#pragma unroll
    for (int w = 0; w < 8; w++) vs += sbuf2[w];
    float rstd = 1.0f / sqrtf(vs * (1.0f / DDIM) + 1e-5f);

    float2 o;
    o.x = dx * rstd * g[t * 2 + 0] + b[t * 2 + 0];
    o.y = dy * rstd * g[t * 2 + 1] + b[t * 2 + 1];
    *(float2*)(y + (size_t)row * DDIM + t * 2) = o;
}

// ---------------- launch ----------------------------------------------------
extern "C" void kernel_launch(void* const* d_in, const int* in_sizes, int n_in,
                              void* d_out, int out_size)
{
    const float* query = (const float*)d_in[0];   // [4,1024,320]
    const float* Wqp   = (const float*)d_in[1];   // [512,320]
    const float* mkeys = (const float*)d_in[2];   // [1024,512]
    const float* mvals = (const float*)d_in[3];   // [1024,512]
    const float* Wq    = (const float*)d_in[4];   // [512,512]
    const float* Wk    = (const float*)d_in[5];
    const float* Wv    = (const float*)d_in[6];
    const float* Wo    = (const float*)d_in[7];
    const float* ln_g  = (const float*)d_in[8];   // [512]
    const float* ln_b  = (const float*)d_in[9];   // [512]
    const float* Wout  = (const float*)d_in[10];  // [320,512]
    const float* bout  = (const float*)d_in[11];  // [320]
    float* out = (float*)d_out;                   // [4,1024,320]

    float *q, *keysN, *valsN, *Kp, *Vp, *qh, *scores, *ctx, *ctxo, *normed;
    int* topidx;
    cudaGetSymbolAddress((void**)&q,      g_q);
    cudaGetSymbolAddress((void**)&keysN,  g_keysN);
    cudaGetSymbolAddress((void**)&valsN,  g_valsN);
    cudaGetSymbolAddress((void**)&Kp,     g_Kp);
    cudaGetSymbolAddress((void**)&Vp,     g_Vp);
    cudaGetSymbolAddress((void**)&qh,     g_qh);
    cudaGetSymbolAddress((void**)&scores, g_scores);
    cudaGetSymbolAddress((void**)&topidx, g_topidx);
    cudaGetSymbolAddress((void**)&ctx,    g_ctx);
    cudaGetSymbolAddress((void**)&ctxo,   g_ctxo);
    cudaGetSymbolAddress((void**)&normed, g_normed);

    // 1) normalize slot tables
    l2norm_kernel<<<dim3(SSLOTS, 2), 256>>>(mkeys, mvals);

    // 2) project slot tables ONCE (replaces per-token gathered projection)
    //    Kp = keysN @ Wk^T, Vp = valsN @ Wv^T  -> fused dual launch, 256 blocks
    gemm_dual_t<64, 64><<<dim3(DDIM / 64, SSLOTS / 64, 2), 64>>>(
        keysN, Wk, Kp, valsN, Wv, Vp, SSLOTS, DDIM, DDIM);

    // 3) q = query @ Wqp^T   [4096,512], K=320
    gemm_t<128, 64><<<dim3(DDIM / 64, TOKS / 128), 128>>>(query, Wqp, q, TOKS, DDIM, QDIM, nullptr);

    // 4) qh = q @ Wq^T       [4096,512]
    gemm_t<128, 64><<<dim3(DDIM / 64, TOKS / 128), 128>>>(q, Wq, qh, TOKS, DDIM, DDIM, nullptr);

    // 5) scores = q @ keysN^T  [4096,1024]
    gemm_t<128, 128><<<dim3(SSLOTS / 128, TOKS / 128), 256>>>(q, keysN, scores, TOKS, SSLOTS, DDIM, nullptr);

    // 6) top-32 per token
    topk_kernel<<<TOKS, 256>>>(scores, topidx);

    // 7) gathered multi-head attention -> ctx [4096,512]
    attn_kernel<<<TOKS, 256>>>(qh, topidx, ctx);

    // 8) ctxo = ctx @ Wo^T
    gemm_t<128, 64><<<dim3(DDIM / 64, TOKS / 128), 128>>>(ctx, Wo, ctxo, TOKS, DDIM, DDIM, nullptr);

    // 9) LayerNorm
    ln_kernel<<<TOKS, 256>>>(ctxo, ln_g, ln_b, normed);

    // 10) out = normed @ Wout^T + bout  [4096,320]  (320 % 64 == 0, no predication)
    gemm_t<128, 64><<<dim3(QDIM / 64, TOKS / 128), 128>>>(normed, Wout, out, TOKS, QDIM, DDIM, bout);
}

// round 3
// speedup vs baseline: 1.1302x; 1.0643x over previous
#include <cuda_runtime.h>
#include <math.h>

// Problem constants
#define TOKS   4096   // B*N
#define DDIM   512
#define SSLOTS 1024
#define QDIM   320
#define KSEL   32
#define NHEAD  8
#define DHEAD  64

typedef unsigned long long u64t;

// ---------------- scratch (device globals; no allocation allowed) ----------
__device__ float g_q[TOKS * DDIM];
__device__ float g_keysN[SSLOTS * DDIM];
__device__ float g_valsN[SSLOTS * DDIM];
__device__ float g_Kp[SSLOTS * DDIM];
__device__ float g_Vp[SSLOTS * DDIM];
__device__ float g_qh[TOKS * DDIM];
__device__ float g_scores[TOKS * SSLOTS];
__device__ float g_ctx[TOKS * DDIM];
__device__ float g_ctxo[TOKS * DDIM];
__device__ float g_normed[TOKS * DDIM];

// ============================================================================
// GEMM NT body: C[tile] = A[M,K] * B[N,K]^T (+bias), BM=128, BN=64, BK=16,
// 128 threads, 8x8 micro-tile computed with packed fma.rn.f32x2.
// ============================================================================
#define BM 128
#define BN 64
#define BK 16

struct GT {
    const float* A;
    const float* B;
    float*       C;
    int N, K;
    const float* bias;
    int tilesX;   // N / 64
};

__device__ __forceinline__ void gemm_body(
    const float* __restrict__ A, const float* __restrict__ B,
    float* __restrict__ C, int N, int K, const float* __restrict__ bias,
    int tileX, int tileY)
{
    constexpr int NT  = 128;
    constexpr int AF4 = BM * BK / 4 / NT;   // 4
    constexpr int BF4 = BN * BK / 4 / NT;   // 2
    constexpr int PAD = 4;

    __shared__ float As[2][BK][BM + PAD];
    __shared__ float Bs[2][BK][BN + PAD];

    const int tid  = threadIdx.x;
    const int tx   = tid & 7;     // 8 col-groups of 8
    const int ty   = tid >> 3;    // 16 row-groups of 8
    const int brow = tileY * BM;
    const int bcol = tileX * BN;

    float4 pa[AF4], pb[BF4];

    auto loadA = [&](int k0) {
#pragma unroll
        for (int i = 0; i < AF4; i++) {
            int slot = tid + i * NT;
            int m = slot >> 2, kq = slot & 3;
            pa[i] = *(const float4*)(A + (size_t)(brow + m) * K + k0 + kq * 4);
        }
    };
    auto loadB = [&](int k0) {
#pragma unroll
        for (int i = 0; i < BF4; i++) {
            int slot = tid + i * NT;
            int n = slot >> 2, kq = slot & 3;
            pb[i] = *(const float4*)(B + (size_t)(bcol + n) * K + k0 + kq * 4);
        }
    };
    auto storeA = [&](int buf) {
#pragma unroll
        for (int i = 0; i < AF4; i++) {
            int slot = tid + i * NT;
            int m = slot >> 2, kq = slot & 3;
            As[buf][kq * 4 + 0][m] = pa[i].x;
            As[buf][kq * 4 + 1][m] = pa[i].y;
            As[buf][kq * 4 + 2][m] = pa[i].z;
            As[buf][kq * 4 + 3][m] = pa[i].w;
        }
    };
    auto storeB = [&](int buf) {
#pragma unroll
        for (int i = 0; i < BF4; i++) {
            int slot = tid + i * NT;
            int n = slot >> 2, kq = slot & 3;
            Bs[buf][kq * 4 + 0][n] = pb[i].x;
            Bs[buf][kq * 4 + 1][n] = pb[i].y;
            Bs[buf][kq * 4 + 2][n] = pb[i].z;
            Bs[buf][kq * 4 + 3][n] = pb[i].w;
        }
    };

    // acc2[i][j] holds packed {C[i][2j], C[i][2j+1]} as f32x2 in a b64 reg
    u64t acc2[8][4];
#pragma unroll
    for (int i = 0; i < 8; i++)
#pragma unroll
        for (int j = 0; j < 4; j++) acc2[i][j] = 0ull;

    const int ntiles = K / BK;
    loadA(0); loadB(0);
    storeA(0); storeB(0);
    __syncthreads();

    for (int t = 0; t < ntiles; t++) {
        const int cur = t & 1;
        const bool more = (t + 1 < ntiles);
        if (more) { loadA((t + 1) * BK); loadB((t + 1) * BK); }

#pragma unroll
        for (int kk = 0; kk < BK; kk++) {
            float4 a0 = *(const float4*)&As[cur][kk][ty * 8];
            float4 a1 = *(const float4*)&As[cur][kk][ty * 8 + 4];
            ulonglong2 bq0 = *(const ulonglong2*)&Bs[cur][kk][tx * 8];
            ulonglong2 bq1 = *(const ulonglong2*)&Bs[cur][kk][tx * 8 + 4];
            u64t bb[4] = {bq0.x, bq0.y, bq1.x, bq1.y};
            float av[8] = {a0.x, a0.y, a0.z, a0.w, a1.x, a1.y, a1.z, a1.w};
#pragma unroll
            for (int i = 0; i < 8; i++) {
                u64t ad;
                asm("mov.b64 %0, {%1, %1};" : "=l"(ad) : "f"(av[i]));
#pragma unroll
                for (int j = 0; j < 4; j++)
                    asm("fma.rn.f32x2 %0, %1, %2, %0;"
                        : "+l"(acc2[i][j]) : "l"(ad), "l"(bb[j]));
            }
        }
        if (more) { storeA(cur ^ 1); storeB(cur ^ 1); }
        __syncthreads();
    }

#pragma unroll
    for (int i = 0; i < 8; i++) {
        const int row = brow + ty * 8 + i;
        const int col = bcol + tx * 8;
        if (bias) {
            // packed bias add (bias 8-float aligned since col % 8 == 0)
            const u64t* bp = (const u64t*)(bias + col);
#pragma unroll
            for (int j = 0; j < 4; j++)
                asm("add.rn.f32x2 %0, %0, %1;" : "+l"(acc2[i][j]) : "l"(bp[j]));
        }
        ulonglong2 o0 = {acc2[i][0], acc2[i][1]};
        ulonglong2 o1 = {acc2[i][2], acc2[i][3]};
        *(ulonglong2*)(C + (size_t)row * N + col)     = o0;
        *(ulonglong2*)(C + (size_t)row * N + col + 4) = o1;
    }
}

// Multi-task GEMM: up to 3 independent NT GEMMs in one launch.
__global__ void __launch_bounds__(128)
gemm3(GT t0, GT t1, GT t2, int e0, int e1)
{
    const int bx = blockIdx.x;
    GT t; int local;
    if (bx < e0)      { t = t0; local = bx; }
    else if (bx < e1) { t = t1; local = bx - e0; }
    else              { t = t2; local = bx - e1; }
    const int tileY = local / t.tilesX;
    const int tileX = local % t.tilesX;
    gemm_body(t.A, t.B, t.C, t.N, t.K, t.bias, tileX, tileY);
}

// ---------------- L2 normalize memory slots (keys & values) ----------------
__global__ __launch_bounds__(256)
void l2norm_kernel(const float* __restrict__ keys, const float* __restrict__ vals)
{
    __shared__ float sbuf[8];
    const int row = blockIdx.x;
    const float* src = (blockIdx.y == 0) ? keys : vals;
    float* dst = (blockIdx.y == 0) ? g_keysN : g_valsN;
    const int t = threadIdx.x;

    float2 v = *(const float2*)(src + (size_t)row * DDIM + t * 2);
    float ss = v.x * v.x + v.y * v.y;
#pragma unroll
    for (int off = 16; off; off >>= 1) ss += __shfl_xor_sync(0xffffffffu, ss, off);
    if ((t & 31) == 0) sbuf[t >> 5] = ss;
    __syncthreads();
    float tot = 0.f;
#pragma unroll
    for (int w = 0; w < 8; w++) tot += sbuf[w];
    float inv = 1.0f / sqrtf(tot + 1e-12f);
    float2 o = make_float2(v.x * inv, v.y * inv);
    *(float2*)(dst + (size_t)row * DDIM + t * 2) = o;
}

// ---------------- fused top-32 + gathered multi-head attention --------------
__global__ __launch_bounds__(256)
void topk_attn_kernel(const float* __restrict__ scores,
                      const float* __restrict__ qh,
                      float* __restrict__ ctx)
{
    __shared__ float s_val[SSLOTS];
    __shared__ float r_val[8];
    __shared__ int   r_idx[8];
    __shared__ int   s_idx[KSEL];
    __shared__ float s_q[DDIM];
    __shared__ float s_w[NHEAD][KSEL];

    const int row = blockIdx.x;
    const int t = threadIdx.x;

    for (int i = t; i < SSLOTS; i += 256)
        s_val[i] = scores[(size_t)row * SSLOTS + i];
    s_q[t]       = qh[(size_t)row * DDIM + t];
    s_q[t + 256] = qh[(size_t)row * DDIM + t + 256];
    __syncthreads();

    // ---- iterative top-32 argmax ----
    for (int sel = 0; sel < KSEL; sel++) {
        float best = -INFINITY;
        int bi = SSLOTS;
        for (int i = t; i < SSLOTS; i += 256) {
            float v = s_val[i];
            if (v > best || (v == best && i < bi)) { best = v; bi = i; }
        }
#pragma unroll
        for (int off = 16; off; off >>= 1) {
            float ov = __shfl_xor_sync(0xffffffffu, best, off);
            int   oi = __shfl_xor_sync(0xffffffffu, bi, off);
            if (ov > best || (ov == best && oi < bi)) { best = ov; bi = oi; }
        }
        if ((t & 31) == 0) { r_val[t >> 5] = best; r_idx[t >> 5] = bi; }
        __syncthreads();
        if (t == 0) {
            float bb = r_val[0];
            int bbi = r_idx[0];
#pragma unroll
            for (int w = 1; w < 8; w++) {
                if (r_val[w] > bb || (r_val[w] == bb && r_idx[w] < bbi)) {
                    bb = r_val[w]; bbi = r_idx[w];
                }
            }
            s_idx[sel] = bbi;
            s_val[bbi] = -INFINITY;
        }
        __syncthreads();
    }

    // ---- attention: one warp per head ----
    const int h = t >> 5;
    const int k = t & 31;
    const float* kp = g_Kp + (size_t)s_idx[k] * DDIM + h * DHEAD;
    const float* qr = &s_q[h * DHEAD];
    float dot = 0.f;
#pragma unroll
    for (int j = 0; j < DHEAD; j += 4) {
        float4 kv = *(const float4*)(kp + j);
        dot += qr[j] * kv.x + qr[j + 1] * kv.y + qr[j + 2] * kv.z + qr[j + 3] * kv.w;
    }
    dot *= 0.125f;  // 1/sqrt(64)

    float m = dot;
#pragma unroll
    for (int off = 16; off; off >>= 1) m = fmaxf(m, __shfl_xor_sync(0xffffffffu, m, off));
    float e = expf(dot - m);
    float s = e;
#pragma unroll
    for (int off = 16; off; off >>= 1) s += __shfl_xor_sync(0xffffffffu, s, off);
    s_w[h][k] = e / s;
    __syncthreads();

#pragma unroll
    for (int rep = 0; rep < 2; rep++) {
        int d = t + rep * 256;
        int hh = d >> 6;
        float acc = 0.f;
#pragma unroll 8
        for (int kk = 0; kk < KSEL; kk++)
            acc += s_w[hh][kk] * g_Vp[(size_t)s_idx[kk] * DDIM + d];
        ctx[(size_t)row * DDIM + d] = acc;
    }
}

// ---------------- LayerNorm over D=512 -------------------------------------
__global__ __launch_bounds__(256)
void ln_kernel(const float* __restrict__ x, const float* __restrict__ g,
               const float* __restrict__ b, float* __restrict__ y)
{
    __shared__ float sbuf[8];
    __shared__ float sbuf2[8];
    const int row = blockIdx.x;
    const int t = threadIdx.x;

    float2 v = *(const float2*)(x + (size_t)row * DDIM + t * 2);
    float s = v.x + v.y;
#pragma unroll
    for (int off = 16; off; off >>= 1) s += __shfl_xor_sync(0xffffffffu, s, off);
    if ((t & 31) == 0) sbuf[t >> 5] = s;
    __syncthreads();
    float tot = 0.f;
#pragma unroll
    for (int w = 0; w < 8; w++) tot += sbuf[w];
    float mu = tot * (1.0f / DDIM);

    float dx = v.x - mu, dy = v.y - mu;
    float ss = dx * dx + dy * dy;
#pragma unroll
    for (int off = 16; off; off >>= 1) ss += __shfl_xor_sync(0xffffffffu, ss, off);
    if ((t & 31) == 0) sbuf2[t >> 5] = ss;
    __syncthreads();
    float vs = 0.f;
#pragma unroll
    for (int w = 0; w < 8; w++) vs += sbuf2[w];
    float rstd = 1.0f / sqrtf(vs * (1.0f / DDIM) + 1e-5f);

    float2 o;
    o.x = dx * rstd * g[t * 2 + 0] + b[t * 2 + 0];
    o.y = dy * rstd * g[t * 2 + 1] + b[t * 2 + 1];
    *(float2*)(y + (size_t)row * DDIM + t * 2) = o;
}

// ---------------- launch ----------------------------------------------------
extern "C" void kernel_launch(void* const* d_in, const int* in_sizes, int n_in,
                              void* d_out, int out_size)
{
    const float* query = (const float*)d_in[0];   // [4,1024,320]
    const float* Wqp   = (const float*)d_in[1];   // [512,320]
    const float* mkeys = (const float*)d_in[2];   // [1024,512]
    const float* mvals = (const float*)d_in[3];   // [1024,512]
    const float* Wq    = (const float*)d_in[4];   // [512,512]
    const float* Wk    = (const float*)d_in[5];
    const float* Wv    = (const float*)d_in[6];
    const float* Wo    = (const float*)d_in[7];
    const float* ln_g  = (const float*)d_in[8];   // [512]
    const float* ln_b  = (const float*)d_in[9];   // [512]
    const float* Wout  = (const float*)d_in[10];  // [320,512]
    const float* bout  = (const float*)d_in[11];  // [320]
    float* out = (float*)d_out;                   // [4,1024,320]

    float *q, *keysN, *valsN, *Kp, *Vp, *qh, *scores, *ctx, *ctxo, *normed;
    cudaGetSymbolAddress((void**)&q,      g_q);
    cudaGetSymbolAddress((void**)&keysN,  g_keysN);
    cudaGetSymbolAddress((void**)&valsN,  g_valsN);
    cudaGetSymbolAddress((void**)&Kp,     g_Kp);
    cudaGetSymbolAddress((void**)&Vp,     g_Vp);
    cudaGetSymbolAddress((void**)&qh,     g_qh);
    cudaGetSymbolAddress((void**)&scores, g_scores);
    cudaGetSymbolAddress((void**)&ctx,    g_ctx);
    cudaGetSymbolAddress((void**)&ctxo,   g_ctxo);
    cudaGetSymbolAddress((void**)&normed, g_normed);

    // 1) normalize slot tables
    l2norm_kernel<<<dim3(SSLOTS, 2), 256>>>(mkeys, mvals);

    // 2) q = query @ Wqp^T, Kp = keysN @ Wk^T, Vp = valsN @ Wv^T (one launch)
    {
        GT tq  = {query, Wqp, q,  DDIM, QDIM, nullptr, DDIM / BN};   // 32*8 = 256 tiles
        GT tkp = {keysN, Wk,  Kp, DDIM, DDIM, nullptr, DDIM / BN};   // 8*8 = 64
        GT tvp = {valsN, Wv,  Vp, DDIM, DDIM, nullptr, DDIM / BN};   // 64
        gemm3<<<256 + 64 + 64, 128>>>(tq, tkp, tvp, 256, 320);
    }

    // 3) qh = q @ Wq^T, scores = q @ keysN^T (one launch)
    {
        GT tqh = {q, Wq,    qh,     DDIM,   DDIM, nullptr, DDIM / BN};    // 256
        GT tsc = {q, keysN, scores, SSLOTS, DDIM, nullptr, SSLOTS / BN};  // 512
        GT dmy = tsc;
        gemm3<<<256 + 512, 128>>>(tqh, tsc, dmy, 256, 768);
    }

    // 4) fused top-32 + attention -> ctx [4096,512]
    topk_attn_kernel<<<TOKS, 256>>>(scores, qh, ctx);

    // 5) ctxo = ctx @ Wo^T
    {
        GT two = {ctx, Wo, ctxo, DDIM, DDIM, nullptr, DDIM / BN};   // 256
        gemm3<<<256, 128>>>(two, two, two, 256, 256);
    }

    // 6) LayerNorm
    ln_kernel<<<TOKS, 256>>>(ctxo, ln_g, ln_b, normed);

    // 7) out = normed @ Wout^T + bout  [4096,320]
    {
        GT tout = {normed, Wout, out, QDIM, DDIM, bout, QDIM / BN}; // 5*32 = 160
        gemm3<<<160, 128>>>(tout, tout, tout, 160, 160);
    }
}

// round 4
// speedup vs baseline: 1.3864x; 1.2267x over previous
#include <cuda_runtime.h>
#include <math.h>

// Problem constants
#define TOKS   4096   // B*N
#define DDIM   512
#define SSLOTS 1024
#define QDIM   320
#define KSEL   32
#define NHEAD  8
#define DHEAD  64

typedef unsigned long long u64t;
typedef unsigned int u32t;

// ---------------- scratch (device globals; no allocation allowed) ----------
__device__ float g_q[TOKS * DDIM];
__device__ float g_keysN[SSLOTS * DDIM];
__device__ float g_valsN[SSLOTS * DDIM];
__device__ float g_Kp[SSLOTS * DDIM];
__device__ float g_Vp[SSLOTS * DDIM];
__device__ float g_qh[TOKS * DDIM];
__device__ float g_scores[TOKS * SSLOTS];
__device__ float g_ctx[TOKS * DDIM];
__device__ float g_ctxo[TOKS * DDIM];
__device__ float g_normed[TOKS * DDIM];

// ============================================================================
// GEMM NT body: C[tile] = A[M,K] * B[N,K]^T (+bias), BM=128, BN=64, BK=16,
// 128 threads, 8x8 micro-tile computed with packed fma.rn.f32x2.
// ============================================================================
#define BM 128
#define BN 64
#define BK 16

struct GT {
    const float* A;
    const float* B;
    float*       C;
    int N, K;
    const float* bias;
    int tilesX;   // N / 64
};

__device__ __forceinline__ void gemm_body(
    const float* __restrict__ A, const float* __restrict__ B,
    float* __restrict__ C, int N, int K, const float* __restrict__ bias,
    int tileX, int tileY)
{
    constexpr int NT  = 128;
    constexpr int AF4 = BM * BK / 4 / NT;   // 4
    constexpr int BF4 = BN * BK / 4 / NT;   // 2
    constexpr int PAD = 4;

    __shared__ float As[2][BK][BM + PAD];
    __shared__ float Bs[2][BK][BN + PAD];

    const int tid  = threadIdx.x;
    const int tx   = tid & 7;     // 8 col-groups of 8
    const int ty   = tid >> 3;    // 16 row-groups of 8
    const int brow = tileY * BM;
    const int bcol = tileX * BN;

    float4 pa[AF4], pb[BF4];

    auto loadA = [&](int k0) {
#pragma unroll
        for (int i = 0; i < AF4; i++) {
            int slot = tid + i * NT;
            int m = slot >> 2, kq = slot & 3;
            pa[i] = *(const float4*)(A + (size_t)(brow + m) * K + k0 + kq * 4);
        }
    };
    auto loadB = [&](int k0) {
#pragma unroll
        for (int i = 0; i < BF4; i++) {
            int slot = tid + i * NT;
            int n = slot >> 2, kq = slot & 3;
            pb[i] = *(const float4*)(B + (size_t)(bcol + n) * K + k0 + kq * 4);
        }
    };
    auto storeA = [&](int buf) {
#pragma unroll
        for (int i = 0; i < AF4; i++) {
            int slot = tid + i * NT;
            int m = slot >> 2, kq = slot & 3;
            As[buf][kq * 4 + 0][m] = pa[i].x;
            As[buf][kq * 4 + 1][m] = pa[i].y;
            As[buf][kq * 4 + 2][m] = pa[i].z;
            As[buf][kq * 4 + 3][m] = pa[i].w;
        }
    };
    auto storeB = [&](int buf) {
#pragma unroll
        for (int i = 0; i < BF4; i++) {
            int slot = tid + i * NT;
            int n = slot >> 2, kq = slot & 3;
            Bs[buf][kq * 4 + 0][n] = pb[i].x;
            Bs[buf][kq * 4 + 1][n] = pb[i].y;
            Bs[buf][kq * 4 + 2][n] = pb[i].z;
            Bs[buf][kq * 4 + 3][n] = pb[i].w;
        }
    };

    u64t acc2[8][4];
#pragma unroll
    for (int i = 0; i < 8; i++)
#pragma unroll
        for (int j = 0; j < 4; j++) acc2[i][j] = 0ull;

    const int ntiles = K / BK;
    loadA(0); loadB(0);
    storeA(0); storeB(0);
    __syncthreads();

    for (int t = 0; t < ntiles; t++) {
        const int cur = t & 1;
        const bool more = (t + 1 < ntiles);
        if (more) { loadA((t + 1) * BK); loadB((t + 1) * BK); }

#pragma unroll
        for (int kk = 0; kk < BK; kk++) {
            float4 a0 = *(const float4*)&As[cur][kk][ty * 8];
            float4 a1 = *(const float4*)&As[cur][kk][ty * 8 + 4];
            ulonglong2 bq0 = *(const ulonglong2*)&Bs[cur][kk][tx * 8];
            ulonglong2 bq1 = *(const ulonglong2*)&Bs[cur][kk][tx * 8 + 4];
            u64t bb[4] = {bq0.x, bq0.y, bq1.x, bq1.y};
            float av[8] = {a0.x, a0.y, a0.z, a0.w, a1.x, a1.y, a1.z, a1.w};
#pragma unroll
            for (int i = 0; i < 8; i++) {
                u64t ad;
                asm("mov.b64 %0, {%1, %1};" : "=l"(ad) : "f"(av[i]));
#pragma unroll
                for (int j = 0; j < 4; j++)
                    asm("fma.rn.f32x2 %0, %1, %2, %0;"
                        : "+l"(acc2[i][j]) : "l"(ad), "l"(bb[j]));
            }
        }
        if (more) { storeA(cur ^ 1); storeB(cur ^ 1); }
        __syncthreads();
    }

#pragma unroll
    for (int i = 0; i < 8; i++) {
        const int row = brow + ty * 8 + i;
        const int col = bcol + tx * 8;
        if (bias) {
            const u64t* bp = (const u64t*)(bias + col);
#pragma unroll
            for (int j = 0; j < 4; j++)
                asm("add.rn.f32x2 %0, %0, %1;" : "+l"(acc2[i][j]) : "l"(bp[j]));
        }
        ulonglong2 o0 = {acc2[i][0], acc2[i][1]};
        ulonglong2 o1 = {acc2[i][2], acc2[i][3]};
        *(ulonglong2*)(C + (size_t)row * N + col)     = o0;
        *(ulonglong2*)(C + (size_t)row * N + col + 4) = o1;
    }
}

__global__ void __launch_bounds__(128)
gemm3(GT t0, GT t1, GT t2, int e0, int e1)
{
    const int bx = blockIdx.x;
    GT t; int local;
    if (bx < e0)      { t = t0; local = bx; }
    else if (bx < e1) { t = t1; local = bx - e0; }
    else              { t = t2; local = bx - e1; }
    const int tileY = local / t.tilesX;
    const int tileX = local % t.tilesX;
    gemm_body(t.A, t.B, t.C, t.N, t.K, t.bias, tileX, tileY);
}

// ---------------- L2 normalize memory slots (keys & values) ----------------
__global__ __launch_bounds__(256)
void l2norm_kernel(const float* __restrict__ keys, const float* __restrict__ vals)
{
    __shared__ float sbuf[8];
    const int row = blockIdx.x;
    const float* src = (blockIdx.y == 0) ? keys : vals;
    float* dst = (blockIdx.y == 0) ? g_keysN : g_valsN;
    const int t = threadIdx.x;

    float2 v = *(const float2*)(src + (size_t)row * DDIM + t * 2);
    float ss = v.x * v.x + v.y * v.y;
#pragma unroll
    for (int off = 16; off; off >>= 1) ss += __shfl_xor_sync(0xffffffffu, ss, off);
    if ((t & 31) == 0) sbuf[t >> 5] = ss;
    __syncthreads();
    float tot = 0.f;
#pragma unroll
    for (int w = 0; w < 8; w++) tot += sbuf[w];
    float inv = 1.0f / sqrtf(tot + 1e-12f);
    float2 o = make_float2(v.x * inv, v.y * inv);
    *(float2*)(dst + (size_t)row * DDIM + t * 2) = o;
}

// ============================================================================
// Fused top-32 (exact 4-pass radix select) + gathered multi-head attention.
// One block of 256 threads per token.
// ============================================================================
__device__ __forceinline__ u32t f2ord(float f) {
    u32t b = __float_as_uint(f);
    return (b & 0x80000000u) ? ~b : (b | 0x80000000u);
}

__global__ __launch_bounds__(256)
void topk_attn_kernel(const float* __restrict__ scores,
                      const float* __restrict__ qh,
                      float* __restrict__ ctx)
{
    __shared__ u32t  s_hist[256];
    __shared__ u32t  s_suf[257];
    __shared__ int   s_idx[KSEL];
    __shared__ int   s_tie[KSEL];
    __shared__ int   s_cnt[2];   // [0]=selected count, [1]=tie count
    __shared__ int   s_T;
    __shared__ float s_q[DDIM];
    __shared__ float s_w[NHEAD][KSEL];

    const int row = blockIdx.x;
    const int t = threadIdx.x;
    const int lane = t & 31;
    const int wrp = t >> 5;

    // load 4 ordered keys per thread (strided) + qh into smem
    u32t u[4];
#pragma unroll
    for (int j = 0; j < 4; j++)
        u[j] = f2ord(scores[(size_t)row * SSLOTS + t + j * 256]);
    s_q[t]       = qh[(size_t)row * DDIM + t];
    s_q[t + 256] = qh[(size_t)row * DDIM + t + 256];
    if (t < 2) s_cnt[t] = 0;

    // ---- 4-pass radix select: find exact 32nd-largest ordered key ----
    u32t prefix = 0;   // high bits fixed so far
    int  need   = KSEL;

#pragma unroll
    for (int b = 3; b >= 0; b--) {
        const int sh = b * 8;
        s_hist[t] = 0;
        __syncthreads();
#pragma unroll
        for (int j = 0; j < 4; j++) {
            bool in = (b == 3) || ((u[j] >> (sh + 8)) == prefix);
            if (in) atomicAdd(&s_hist[(u[j] >> sh) & 255u], 1u);
        }
        __syncthreads();
        // two-level suffix scan: s_suf[i] = sum of hist[i..255]
        {
            u32t v = s_hist[t];
#pragma unroll
            for (int off = 1; off < 32; off <<= 1) {
                u32t o = __shfl_down_sync(0xffffffffu, v, off);
                if (lane + off < 32) v += o;
            }
            __shared__ u32t wsum[8];
            if (lane == 0) wsum[wrp] = v;
            __syncthreads();
            u32t woff = 0;
#pragma unroll
            for (int w = 0; w < 8; w++) woff += (w > wrp) ? wsum[w] : 0u;
            s_suf[t] = v + woff;
            if (t == 0) s_suf[256] = 0;
        }
        __syncthreads();
        // threshold byte: unique T with suf[T] >= need > suf[T+1]
        if (s_suf[t] >= (u32t)need && s_suf[t + 1] < (u32t)need) s_T = t;
        __syncthreads();
        const int T = s_T;
        need -= (int)s_suf[T + 1];
        prefix = (prefix << 8) | (u32t)T;
        __syncthreads();
    }
    const u32t V = prefix;   // exact threshold value; `need` ties to take

    // ---- collect: strictly greater -> selected; equal -> tie list ----
#pragma unroll
    for (int j = 0; j < 4; j++) {
        if (u[j] > V) {
            int p = atomicAdd(&s_cnt[0], 1);
            s_idx[p] = t + j * 256;
        } else if (u[j] == V) {
            int p = atomicAdd(&s_cnt[1], 1);
            if (p < KSEL) s_tie[p] = t + j * 256;
        }
    }
    __syncthreads();
    if (t == 0) {
        // take `need` lowest indices among ties (jax top_k boundary semantics)
        int nt = min(s_cnt[1], KSEL);
        int base = s_cnt[0];
        for (int r = 0; r < need; r++) {
            int best = 1 << 30, bj = -1;
            for (int j = 0; j < nt; j++)
                if (s_tie[j] < best) { best = s_tie[j]; bj = j; }
            s_idx[base + r] = best;
            s_tie[bj] = 1 << 30;
        }
    }
    __syncthreads();

    // ---- attention: one warp per head ----
    const int h = wrp;
    const int k = lane;
    const float* kp = g_Kp + (size_t)s_idx[k] * DDIM + h * DHEAD;
    const float* qr = &s_q[h * DHEAD];
    float dot = 0.f;
#pragma unroll
    for (int j = 0; j < DHEAD; j += 4) {
        float4 kv = *(const float4*)(kp + j);
        dot += qr[j] * kv.x + qr[j + 1] * kv.y + qr[j + 2] * kv.z + qr[j + 3] * kv.w;
    }
    dot *= 0.125f;  // 1/sqrt(64)

    float m = dot;
#pragma unroll
    for (int off = 16; off; off >>= 1) m = fmaxf(m, __shfl_xor_sync(0xffffffffu, m, off));
    float e = expf(dot - m);
    float s = e;
#pragma unroll
    for (int off = 16; off; off >>= 1) s += __shfl_xor_sync(0xffffffffu, s, off);
    s_w[h][k] = e / s;
    __syncthreads();

    // ctx: each thread owns 2 consecutive dims (float2)
    {
        const int d2 = t * 2;
        const int hh = t >> 5;   // (t*2)>>6
        float2 acc = make_float2(0.f, 0.f);
#pragma unroll 8
        for (int kk = 0; kk < KSEL; kk++) {
            float w = s_w[hh][kk];
            float2 v = *(const float2*)(g_Vp + (size_t)s_idx[kk] * DDIM + d2);
            acc.x = fmaf(w, v.x, acc.x);
            acc.y = fmaf(w, v.y, acc.y);
        }
        *(float2*)(ctx + (size_t)row * DDIM + d2) = acc;
    }
}

// ---------------- LayerNorm over D=512 -------------------------------------
__global__ __launch_bounds__(256)
void ln_kernel(const float* __restrict__ x, const float* __restrict__ g,
               const float* __restrict__ b, float* __restrict__ y)
{
    __shared__ float sbuf[8];
    __shared__ float sbuf2[8];
    const int row = blockIdx.x;
    const int t = threadIdx.x;

    float2 v = *(const float2*)(x + (size_t)row * DDIM + t * 2);
    float s = v.x + v.y;
#pragma unroll
    for (int off = 16; off; off >>= 1) s += __shfl_xor_sync(0xffffffffu, s, off);
    if ((t & 31) == 0) sbuf[t >> 5] = s;
    __syncthreads();
    float tot = 0.f;
#pragma unroll
    for (int w = 0; w < 8; w++) tot += sbuf[w];
    float mu = tot * (1.0f / DDIM);

    float dx = v.x - mu, dy = v.y - mu;
    float ss = dx * dx + dy * dy;
#pragma unroll
    for (int off = 16; off; off >>= 1) ss += __shfl_xor_sync(0xffffffffu, ss, off);
    if ((t & 31) == 0) sbuf2[t >> 5] = ss;
    __syncthreads();
    float vs = 0.f;
#pragma unroll
    for (int w = 0; w < 8; w++) vs += sbuf2[w];
    float rstd = 1.0f / sqrtf(vs * (1.0f / DDIM) + 1e-5f);

    float2 o;
    o.x = dx * rstd * g[t * 2 + 0] + b[t * 2 + 0];
    o.y = dy * rstd * g[t * 2 + 1] + b[t * 2 + 1];
    *(float2*)(y + (size_t)row * DDIM + t * 2) = o;
}

// ---------------- launch ----------------------------------------------------
extern "C" void kernel_launch(void* const* d_in, const int* in_sizes, int n_in,
                              void* d_out, int out_size)
{
    const float* query = (const float*)d_in[0];   // [4,1024,320]
    const float* Wqp   = (const float*)d_in[1];   // [512,320]
    const float* mkeys = (const float*)d_in[2];   // [1024,512]
    const float* mvals = (const float*)d_in[3];   // [1024,512]
    const float* Wq    = (const float*)d_in[4];   // [512,512]
    const float* Wk    = (const float*)d_in[5];
    const float* Wv    = (const float*)d_in[6];
    const float* Wo    = (const float*)d_in[7];
    const float* ln_g  = (const float*)d_in[8];   // [512]
    const float* ln_b  = (const float*)d_in[9];   // [512]
    const float* Wout  = (const float*)d_in[10];  // [320,512]
    const float* bout  = (const float*)d_in[11];  // [320]
    float* out = (float*)d_out;                   // [4,1024,320]

    float *q, *keysN, *valsN, *Kp, *Vp, *qh, *scores, *ctx, *ctxo, *normed;
    cudaGetSymbolAddress((void**)&q,      g_q);
    cudaGetSymbolAddress((void**)&keysN,  g_keysN);
    cudaGetSymbolAddress((void**)&valsN,  g_valsN);
    cudaGetSymbolAddress((void**)&Kp,     g_Kp);
    cudaGetSymbolAddress((void**)&Vp,     g_Vp);
    cudaGetSymbolAddress((void**)&qh,     g_qh);
    cudaGetSymbolAddress((void**)&scores, g_scores);
    cudaGetSymbolAddress((void**)&ctx,    g_ctx);
    cudaGetSymbolAddress((void**)&ctxo,   g_ctxo);
    cudaGetSymbolAddress((void**)&normed, g_normed);

    // 1) normalize slot tables
    l2norm_kernel<<<dim3(SSLOTS, 2), 256>>>(mkeys, mvals);

    // 2) q = query @ Wqp^T, Kp = keysN @ Wk^T, Vp = valsN @ Wv^T (one launch)
    {
        GT tq  = {query, Wqp, q,  DDIM, QDIM, nullptr, DDIM / BN};   // 256 tiles
        GT tkp = {keysN, Wk,  Kp, DDIM, DDIM, nullptr, DDIM / BN};   // 64
        GT tvp = {valsN, Wv,  Vp, DDIM, DDIM, nullptr, DDIM / BN};   // 64
        gemm3<<<256 + 64 + 64, 128>>>(tq, tkp, tvp, 256, 320);
    }

    // 3) qh = q @ Wq^T, scores = q @ keysN^T (one launch)
    {
        GT tqh = {q, Wq,    qh,     DDIM,   DDIM, nullptr, DDIM / BN};    // 256
        GT tsc = {q, keysN, scores, SSLOTS, DDIM, nullptr, SSLOTS / BN};  // 512
        GT dmy = tsc;
        gemm3<<<256 + 512, 128>>>(tqh, tsc, dmy, 256, 768);
    }

    // 4) fused radix-select top-32 + attention -> ctx [4096,512]
    topk_attn_kernel<<<TOKS, 256>>>(scores, qh, ctx);

    // 5) ctxo = ctx @ Wo^T
    {
        GT two = {ctx, Wo, ctxo, DDIM, DDIM, nullptr, DDIM / BN};   // 256
        gemm3<<<256, 128>>>(two, two, two, 256, 256);
    }

    // 6) LayerNorm
    ln_kernel<<<TOKS, 256>>>(ctxo, ln_g, ln_b, normed);

    // 7) out = normed @ Wout^T + bout  [4096,320]
    {
        GT tout = {normed, Wout, out, QDIM, DDIM, bout, QDIM / BN}; // 160
        gemm3<<<160, 128>>>(tout, tout, tout, 160, 160);
    }
}

// round 5
// speedup vs baseline: 1.5231x; 1.0986x over previous
#include <cuda_runtime.h>
#include <math.h>

// Problem constants
#define TOKS   4096   // B*N
#define DDIM   512
#define SSLOTS 1024
#define QDIM   320
#define KSEL   32
#define NHEAD  8
#define DHEAD  64

typedef unsigned long long u64t;
typedef unsigned int u32t;

// ---------------- scratch (device globals; no allocation allowed) ----------
__device__ float g_q[TOKS * DDIM];
__device__ float g_keysN[SSLOTS * DDIM];
__device__ float g_valsN[SSLOTS * DDIM];
__device__ float g_Kp[SSLOTS * DDIM];
__device__ float g_Vp[SSLOTS * DDIM];
__device__ float g_qh[TOKS * DDIM];
__device__ float g_scores[TOKS * SSLOTS];
__device__ float g_ctx[TOKS * DDIM];
__device__ float g_ctxo[TOKS * DDIM];
__device__ float g_normed[TOKS * DDIM];

// ============================================================================
// GEMM NT body: C[tile] = A[M,K] * B[N,K]^T (+bias), BM=128, BN=64, BK=16,
// 128 threads, 8x8 micro-tile computed with packed fma.rn.f32x2.
// ============================================================================
#define BM 128
#define BN 64
#define BK 16

struct GT {
    const float* A;
    const float* B;
    float*       C;
    int N, K;
    const float* bias;
    int tilesX;   // N / 64
};

__device__ __forceinline__ void gemm_body(
    const float* __restrict__ A, const float* __restrict__ B,
    float* __restrict__ C, int N, int K, const float* __restrict__ bias,
    int tileX, int tileY)
{
    constexpr int NT  = 128;
    constexpr int AF4 = BM * BK / 4 / NT;   // 4
    constexpr int BF4 = BN * BK / 4 / NT;   // 2
    constexpr int PAD = 4;

    __shared__ float As[2][BK][BM + PAD];
    __shared__ float Bs[2][BK][BN + PAD];

    const int tid  = threadIdx.x;
    const int tx   = tid & 7;
    const int ty   = tid >> 3;
    const int brow = tileY * BM;
    const int bcol = tileX * BN;

    float4 pa[AF4], pb[BF4];

    auto loadA = [&](int k0) {
#pragma unroll
        for (int i = 0; i < AF4; i++) {
            int slot = tid + i * NT;
            int m = slot >> 2, kq = slot & 3;
            pa[i] = *(const float4*)(A + (size_t)(brow + m) * K + k0 + kq * 4);
        }
    };
    auto loadB = [&](int k0) {
#pragma unroll
        for (int i = 0; i < BF4; i++) {
            int slot = tid + i * NT;
            int n = slot >> 2, kq = slot & 3;
            pb[i] = *(const float4*)(B + (size_t)(bcol + n) * K + k0 + kq * 4);
        }
    };
    auto storeA = [&](int buf) {
#pragma unroll
        for (int i = 0; i < AF4; i++) {
            int slot = tid + i * NT;
            int m = slot >> 2, kq = slot & 3;
            As[buf][kq * 4 + 0][m] = pa[i].x;
            As[buf][kq * 4 + 1][m] = pa[i].y;
            As[buf][kq * 4 + 2][m] = pa[i].z;
            As[buf][kq * 4 + 3][m] = pa[i].w;
        }
    };
    auto storeB = [&](int buf) {
#pragma unroll
        for (int i = 0; i < BF4; i++) {
            int slot = tid + i * NT;
            int n = slot >> 2, kq = slot & 3;
            Bs[buf][kq * 4 + 0][n] = pb[i].x;
            Bs[buf][kq * 4 + 1][n] = pb[i].y;
            Bs[buf][kq * 4 + 2][n] = pb[i].z;
            Bs[buf][kq * 4 + 3][n] = pb[i].w;
        }
    };

    u64t acc2[8][4];
#pragma unroll
    for (int i = 0; i < 8; i++)
#pragma unroll
        for (int j = 0; j < 4; j++) acc2[i][j] = 0ull;

    const int ntiles = K / BK;
    loadA(0); loadB(0);
    storeA(0); storeB(0);
    __syncthreads();

    for (int t = 0; t < ntiles; t++) {
        const int cur = t & 1;
        const bool more = (t + 1 < ntiles);
        if (more) { loadA((t + 1) * BK); loadB((t + 1) * BK); }

#pragma unroll
        for (int kk = 0; kk < BK; kk++) {
            float4 a0 = *(const float4*)&As[cur][kk][ty * 8];
            float4 a1 = *(const float4*)&As[cur][kk][ty * 8 + 4];
            ulonglong2 bq0 = *(const ulonglong2*)&Bs[cur][kk][tx * 8];
            ulonglong2 bq1 = *(const ulonglong2*)&Bs[cur][kk][tx * 8 + 4];
            u64t bb[4] = {bq0.x, bq0.y, bq1.x, bq1.y};
            float av[8] = {a0.x, a0.y, a0.z, a0.w, a1.x, a1.y, a1.z, a1.w};
#pragma unroll
            for (int i = 0; i < 8; i++) {
                u64t ad;
                asm("mov.b64 %0, {%1, %1};" : "=l"(ad) : "f"(av[i]));
#pragma unroll
                for (int j = 0; j < 4; j++)
                    asm("fma.rn.f32x2 %0, %1, %2, %0;"
                        : "+l"(acc2[i][j]) : "l"(ad), "l"(bb[j]));
            }
        }
        if (more) { storeA(cur ^ 1); storeB(cur ^ 1); }
        __syncthreads();
    }

#pragma unroll
    for (int i = 0; i < 8; i++) {
        const int row = brow + ty * 8 + i;
        const int col = bcol + tx * 8;
        if (bias) {
            const u64t* bp = (const u64t*)(bias + col);
#pragma unroll
            for (int j = 0; j < 4; j++)
                asm("add.rn.f32x2 %0, %0, %1;" : "+l"(acc2[i][j]) : "l"(bp[j]));
        }
        ulonglong2 o0 = {acc2[i][0], acc2[i][1]};
        ulonglong2 o1 = {acc2[i][2], acc2[i][3]};
        *(ulonglong2*)(C + (size_t)row * N + col)     = o0;
        *(ulonglong2*)(C + (size_t)row * N + col + 4) = o1;
    }
}

__global__ void __launch_bounds__(128)
gemm3(GT t0, GT t1, GT t2, int e0, int e1)
{
    const int bx = blockIdx.x;
    GT t; int local;
    if (bx < e0)      { t = t0; local = bx; }
    else if (bx < e1) { t = t1; local = bx - e0; }
    else              { t = t2; local = bx - e1; }
    const int tileY = local / t.tilesX;
    const int tileX = local % t.tilesX;
    gemm_body(t.A, t.B, t.C, t.N, t.K, t.bias, tileX, tileY);
}

// ---------------- L2 normalize memory slots (keys & values) ----------------
__global__ __launch_bounds__(256)
void l2norm_kernel(const float* __restrict__ keys, const float* __restrict__ vals)
{
    __shared__ float sbuf[8];
    const int row = blockIdx.x;
    const float* src = (blockIdx.y == 0) ? keys : vals;
    float* dst = (blockIdx.y == 0) ? g_keysN : g_valsN;
    const int t = threadIdx.x;

    float2 v = *(const float2*)(src + (size_t)row * DDIM + t * 2);
    float ss = v.x * v.x + v.y * v.y;
#pragma unroll
    for (int off = 16; off; off >>= 1) ss += __shfl_xor_sync(0xffffffffu, ss, off);
    if ((t & 31) == 0) sbuf[t >> 5] = ss;
    __syncthreads();
    float tot = 0.f;
#pragma unroll
    for (int w = 0; w < 8; w++) tot += sbuf[w];
    float inv = 1.0f / sqrtf(tot + 1e-12f);
    float2 o = make_float2(v.x * inv, v.y * inv);
    *(float2*)(dst + (size_t)row * DDIM + t * 2) = o;
}

// ============================================================================
// Fused top-32 (exact 4-pass radix select) + gathered multi-head attention.
// One block of 256 threads per token. Attention loads fully coalesced.
// ============================================================================
__device__ __forceinline__ u32t f2ord(float f) {
    u32t b = __float_as_uint(f);
    return (b & 0x80000000u) ? ~b : (b | 0x80000000u);
}

__global__ __launch_bounds__(256)
void topk_attn_kernel(const float* __restrict__ scores,
                      const float* __restrict__ qh,
                      float* __restrict__ ctx)
{
    __shared__ u32t  s_hist[256];
    __shared__ u32t  s_suf[257];
    __shared__ int   s_idx[KSEL];
    __shared__ int   s_tie[KSEL];
    __shared__ int   s_cnt[2];
    __shared__ int   s_T;
    __shared__ float s_q[DDIM];
    __shared__ float s_dot[NHEAD][KSEL];

    const int row = blockIdx.x;
    const int t = threadIdx.x;
    const int lane = t & 31;
    const int wrp = t >> 5;

    // load 4 ordered keys per thread (strided) + qh into smem
    u32t u[4];
#pragma unroll
    for (int j = 0; j < 4; j++)
        u[j] = f2ord(scores[(size_t)row * SSLOTS + t + j * 256]);
    s_q[t]       = qh[(size_t)row * DDIM + t];
    s_q[t + 256] = qh[(size_t)row * DDIM + t + 256];
    if (t < 2) s_cnt[t] = 0;

    // ---- 4-pass radix select: find exact 32nd-largest ordered key ----
    u32t prefix = 0;
    int  need   = KSEL;

#pragma unroll
    for (int b = 3; b >= 0; b--) {
        const int sh = b * 8;
        s_hist[t] = 0;
        __syncthreads();
#pragma unroll
        for (int j = 0; j < 4; j++) {
            bool in = (b == 3) || ((u[j] >> (sh + 8)) == prefix);
            if (in) atomicAdd(&s_hist[(u[j] >> sh) & 255u], 1u);
        }
        __syncthreads();
        // two-level suffix scan: s_suf[i] = sum of hist[i..255]
        {
            u32t v = s_hist[t];
#pragma unroll
            for (int off = 1; off < 32; off <<= 1) {
                u32t o = __shfl_down_sync(0xffffffffu, v, off);
                if (lane + off < 32) v += o;
            }
            __shared__ u32t wsum[8];
            if (lane == 0) wsum[wrp] = v;
            __syncthreads();
            u32t woff = 0;
#pragma unroll
            for (int w = 0; w < 8; w++) woff += (w > wrp) ? wsum[w] : 0u;
            s_suf[t] = v + woff;
            if (t == 0) s_suf[256] = 0;
        }
        __syncthreads();
        if (s_suf[t] >= (u32t)need && s_suf[t + 1] < (u32t)need) s_T = t;
        __syncthreads();
        const int T = s_T;
        need -= (int)s_suf[T + 1];
        prefix = (prefix << 8) | (u32t)T;
        __syncthreads();
    }
    const u32t V = prefix;

    // ---- collect: strictly greater -> selected; equal -> tie list ----
#pragma unroll
    for (int j = 0; j < 4; j++) {
        if (u[j] > V) {
            int p = atomicAdd(&s_cnt[0], 1);
            s_idx[p] = t + j * 256;
        } else if (u[j] == V) {
            int p = atomicAdd(&s_cnt[1], 1);
            if (p < KSEL) s_tie[p] = t + j * 256;
        }
    }
    __syncthreads();
    if (t == 0) {
        int nt = min(s_cnt[1], KSEL);
        int base = s_cnt[0];
        for (int r = 0; r < need; r++) {
            int best = 1 << 30, bj = -1;
            for (int j = 0; j < nt; j++)
                if (s_tie[j] < best) { best = s_tie[j]; bj = j; }
            s_idx[base + r] = best;
            s_tie[bj] = 1 << 30;
        }
    }
    __syncthreads();

    // ---- attention: warp = head; coalesced cooperative dots ----
    const int h  = wrp;
    const int g  = lane >> 4;     // 2 slot-groups of 16 lanes
    const int gl = lane & 15;     // lane within group

    const int myidx = s_idx[lane];   // lane k holds selected slot k's row

    // q fragment for this lane's group position (same for both groups)
    float4 qv = *(const float4*)&s_q[h * DHEAD + gl * 4];

#pragma unroll
    for (int i = 0; i < 16; i++) {
        const int slot = i * 2 + g;
        const int rowi = __shfl_sync(0xffffffffu, myidx, slot);
        float4 kv = *(const float4*)(g_Kp + (size_t)rowi * DDIM + h * DHEAD + gl * 4);
        float p = qv.x * kv.x + qv.y * kv.y + qv.z * kv.z + qv.w * kv.w;
        p += __shfl_xor_sync(0xffffffffu, p, 8);
        p += __shfl_xor_sync(0xffffffffu, p, 4);
        p += __shfl_xor_sync(0xffffffffu, p, 2);
        p += __shfl_xor_sync(0xffffffffu, p, 1);
        if (gl == 0) s_dot[h][slot] = p;
    }
    __syncwarp();

    // softmax over 32 slots, weights register-resident (lane k -> slot k)
    float dot = s_dot[h][lane] * 0.125f;   // 1/sqrt(64)
    float m = dot;
#pragma unroll
    for (int off = 16; off; off >>= 1) m = fmaxf(m, __shfl_xor_sync(0xffffffffu, m, off));
    float e = expf(dot - m);
    float s = e;
#pragma unroll
    for (int off = 16; off; off >>= 1) s += __shfl_xor_sync(0xffffffffu, s, off);
    const float myw = e / s;

    // ctx: warp w owns dims [w*64, w*64+64) == head w. Coalesced V reads,
    // weights broadcast by shuffle. No cross-warp dependency -> no barrier.
    {
        const int d2 = t * 2;
        float2 acc = make_float2(0.f, 0.f);
#pragma unroll 8
        for (int kk = 0; kk < KSEL; kk++) {
            const float wv = __shfl_sync(0xffffffffu, myw, kk);
            const int rk = __shfl_sync(0xffffffffu, myidx, kk);
            float2 v = *(const float2*)(g_Vp + (size_t)rk * DDIM + d2);
            acc.x = fmaf(wv, v.x, acc.x);
            acc.y = fmaf(wv, v.y, acc.y);
        }
        *(float2*)(ctx + (size_t)row * DDIM + d2) = acc;
    }
}

// ---------------- LayerNorm over D=512 -------------------------------------
__global__ __launch_bounds__(256)
void ln_kernel(const float* __restrict__ x, const float* __restrict__ g,
               const float* __restrict__ b, float* __restrict__ y)
{
    __shared__ float sbuf[8];
    __shared__ float sbuf2[8];
    const int row = blockIdx.x;
    const int t = threadIdx.x;

    float2 v = *(const float2*)(x + (size_t)row * DDIM + t * 2);
    float s = v.x + v.y;
#pragma unroll
    for (int off = 16; off; off >>= 1) s += __shfl_xor_sync(0xffffffffu, s, off);
    if ((t & 31) == 0) sbuf[t >> 5] = s;
    __syncthreads();
    float tot = 0.f;
#pragma unroll
    for (int w = 0; w < 8; w++) tot += sbuf[w];
    float mu = tot * (1.0f / DDIM);

    float dx = v.x - mu, dy = v.y - mu;
    float ss = dx * dx + dy * dy;
#pragma unroll
    for (int off = 16; off; off >>= 1) ss += __shfl_xor_sync(0xffffffffu, ss, off);
    if ((t & 31) == 0) sbuf2[t >> 5] = ss;
    __syncthreads();
    float vs = 0.f;
#pragma unroll
    for (int w = 0; w < 8; w++) vs += sbuf2[w];
    float rstd = 1.0f / sqrtf(vs * (1.0f / DDIM) + 1e-5f);

    float2 o;
    o.x = dx * rstd * g[t * 2 + 0] + b[t * 2 + 0];
    o.y = dy * rstd * g[t * 2 + 1] + b[t * 2 + 1];
    *(float2*)(y + (size_t)row * DDIM + t * 2) = o;
}

// ---------------- launch ----------------------------------------------------
extern "C" void kernel_launch(void* const* d_in, const int* in_sizes, int n_in,
                              void* d_out, int out_size)
{
    const float* query = (const float*)d_in[0];
    const float* Wqp   = (const float*)d_in[1];
    const float* mkeys = (const float*)d_in[2];
    const float* mvals = (const float*)d_in[3];
    const float* Wq    = (const float*)d_in[4];
    const float* Wk    = (const float*)d_in[5];
    const float* Wv    = (const float*)d_in[6];
    const float* Wo    = (const float*)d_in[7];
    const float* ln_g  = (const float*)d_in[8];
    const float* ln_b  = (const float*)d_in[9];
    const float* Wout  = (const float*)d_in[10];
    const float* bout  = (const float*)d_in[11];
    float* out = (float*)d_out;

    float *q, *keysN, *valsN, *Kp, *Vp, *qh, *scores, *ctx, *ctxo, *normed;
    cudaGetSymbolAddress((void**)&q,      g_q);
    cudaGetSymbolAddress((void**)&keysN,  g_keysN);
    cudaGetSymbolAddress((void**)&valsN,  g_valsN);
    cudaGetSymbolAddress((void**)&Kp,     g_Kp);
    cudaGetSymbolAddress((void**)&Vp,     g_Vp);
    cudaGetSymbolAddress((void**)&qh,     g_qh);
    cudaGetSymbolAddress((void**)&scores, g_scores);
    cudaGetSymbolAddress((void**)&ctx,    g_ctx);
    cudaGetSymbolAddress((void**)&ctxo,   g_ctxo);
    cudaGetSymbolAddress((void**)&normed, g_normed);

    // 1) normalize slot tables
    l2norm_kernel<<<dim3(SSLOTS, 2), 256>>>(mkeys, mvals);

    // 2) q = query @ Wqp^T, Kp = keysN @ Wk^T, Vp = valsN @ Wv^T (one launch)
    {
        GT tq  = {query, Wqp, q,  DDIM, QDIM, nullptr, DDIM / BN};
        GT tkp = {keysN, Wk,  Kp, DDIM, DDIM, nullptr, DDIM / BN};
        GT tvp = {valsN, Wv,  Vp, DDIM, DDIM, nullptr, DDIM / BN};
        gemm3<<<256 + 64 + 64, 128>>>(tq, tkp, tvp, 256, 320);
    }

    // 3) qh = q @ Wq^T, scores = q @ keysN^T (one launch)
    {
        GT tqh = {q, Wq,    qh,     DDIM,   DDIM, nullptr, DDIM / BN};
        GT tsc = {q, keysN, scores, SSLOTS, DDIM, nullptr, SSLOTS / BN};
        GT dmy = tsc;
        gemm3<<<256 + 512, 128>>>(tqh, tsc, dmy, 256, 768);
    }

    // 4) fused radix-select top-32 + attention -> ctx [4096,512]
    topk_attn_kernel<<<TOKS, 256>>>(scores, qh, ctx);

    // 5) ctxo = ctx @ Wo^T
    {
        GT two = {ctx, Wo, ctxo, DDIM, DDIM, nullptr, DDIM / BN};
        gemm3<<<256, 128>>>(two, two, two, 256, 256);
    }

    // 6) LayerNorm
    ln_kernel<<<TOKS, 256>>>(ctxo, ln_g, ln_b, normed);

    // 7) out = normed @ Wout^T + bout  [4096,320]
    {
        GT tout = {normed, Wout, out, QDIM, DDIM, bout, QDIM / BN};
        gemm3<<<160, 128>>>(tout, tout, tout, 160, 160);
    }
}

// round 6
// speedup vs baseline: 1.5838x; 1.0398x over previous
#include <cuda_runtime.h>
#include <math.h>

// Problem constants
#define TOKS   4096   // B*N
#define DDIM   512
#define SSLOTS 1024
#define QDIM   320
#define KSEL   32
#define NHEAD  8
#define DHEAD  64

typedef unsigned long long u64t;
typedef unsigned int u32t;

// ---------------- scratch (device globals; no allocation allowed) ----------
__device__ float g_q[TOKS * DDIM];
__device__ float g_keysN[SSLOTS * DDIM];
__device__ float g_valsN[SSLOTS * DDIM];
__device__ float g_Kp[SSLOTS * DDIM];
__device__ float g_Vp[SSLOTS * DDIM];
__device__ float g_qh[TOKS * DDIM];
__device__ float g_scores[TOKS * SSLOTS];
__device__ float g_ctx[TOKS * DDIM];
__device__ float g_ctxo[TOKS * DDIM];
__device__ float g_normed[TOKS * DDIM];
__device__ float g_WqpT[QDIM * DDIM];   // Wqp transposed [320,512]
__device__ float g_Wqq[DDIM * QDIM];    // Wq @ Wqp       [512,320]

// ============================================================================
// GEMM NT: C[64x64 tile] = A[M,K] * B[N,K]^T (+bias). BM=BN=64, BK=16,
// 64 threads, 8x8 micro-tile with packed fma.rn.f32x2. Fine-grained blocks
// (5/SM) minimize wave-quantization tails.
// ============================================================================
#define BM 64
#define BN 64
#define BK 16
#define NT 64     // threads per block
#define AF4 4     // BM*BK/4/NT
#define BF4 4

struct GT {
    const float* A;
    const float* B;
    float*       C;
    int N, K;
    const float* bias;
    int tilesX;   // N / 64
};

__device__ __forceinline__ void gemm_body(
    const float* __restrict__ A, const float* __restrict__ B,
    float* __restrict__ C, int N, int K, const float* __restrict__ bias,
    int tileX, int tileY)
{
    constexpr int PAD = 4;
    __shared__ float As[2][BK][BM + PAD];
    __shared__ float Bs[2][BK][BN + PAD];

    const int tid  = threadIdx.x;
    const int tx   = tid & 7;     // 8 col-groups of 8
    const int ty   = tid >> 3;    // 8 row-groups of 8
    const int brow = tileY * BM;
    const int bcol = tileX * BN;

    float4 pa[AF4], pb[BF4];

    auto loadA = [&](int k0) {
#pragma unroll
        for (int i = 0; i < AF4; i++) {
            int slot = tid + i * NT;
            int m = slot >> 2, kq = slot & 3;
            pa[i] = *(const float4*)(A + (size_t)(brow + m) * K + k0 + kq * 4);
        }
    };
    auto loadB = [&](int k0) {
#pragma unroll
        for (int i = 0; i < BF4; i++) {
            int slot = tid + i * NT;
            int n = slot >> 2, kq = slot & 3;
            pb[i] = *(const float4*)(B + (size_t)(bcol + n) * K + k0 + kq * 4);
        }
    };
    auto storeA = [&](int buf) {
#pragma unroll
        for (int i = 0; i < AF4; i++) {
            int slot = tid + i * NT;
            int m = slot >> 2, kq = slot & 3;
            As[buf][kq * 4 + 0][m] = pa[i].x;
            As[buf][kq * 4 + 1][m] = pa[i].y;
            As[buf][kq * 4 + 2][m] = pa[i].z;
            As[buf][kq * 4 + 3][m] = pa[i].w;
        }
    };
    auto storeB = [&](int buf) {
#pragma unroll
        for (int i = 0; i < BF4; i++) {
            int slot = tid + i * NT;
            int n = slot >> 2, kq = slot & 3;
            Bs[buf][kq * 4 + 0][n] = pb[i].x;
            Bs[buf][kq * 4 + 1][n] = pb[i].y;
            Bs[buf][kq * 4 + 2][n] = pb[i].z;
            Bs[buf][kq * 4 + 3][n] = pb[i].w;
        }
    };

    u64t acc2[8][4];
#pragma unroll
    for (int i = 0; i < 8; i++)
#pragma unroll
        for (int j = 0; j < 4; j++) acc2[i][j] = 0ull;

    const int ntiles = K / BK;
    loadA(0); loadB(0);
    storeA(0); storeB(0);
    __syncthreads();

    for (int t = 0; t < ntiles; t++) {
        const int cur = t & 1;
        const bool more = (t + 1 < ntiles);
        if (more) { loadA((t + 1) * BK); loadB((t + 1) * BK); }

#pragma unroll
        for (int kk = 0; kk < BK; kk++) {
            float4 a0 = *(const float4*)&As[cur][kk][ty * 8];
            float4 a1 = *(const float4*)&As[cur][kk][ty * 8 + 4];
            ulonglong2 bq0 = *(const ulonglong2*)&Bs[cur][kk][tx * 8];
            ulonglong2 bq1 = *(const ulonglong2*)&Bs[cur][kk][tx * 8 + 4];
            u64t bb[4] = {bq0.x, bq0.y, bq1.x, bq1.y};
            float av[8] = {a0.x, a0.y, a0.z, a0.w, a1.x, a1.y, a1.z, a1.w};
#pragma unroll
            for (int i = 0; i < 8; i++) {
                u64t ad;
                asm("mov.b64 %0, {%1, %1};" : "=l"(ad) : "f"(av[i]));
#pragma unroll
                for (int j = 0; j < 4; j++)
                    asm("fma.rn.f32x2 %0, %1, %2, %0;"
                        : "+l"(acc2[i][j]) : "l"(ad), "l"(bb[j]));
            }
        }
        if (more) { storeA(cur ^ 1); storeB(cur ^ 1); }
        __syncthreads();
    }

#pragma unroll
    for (int i = 0; i < 8; i++) {
        const int row = brow + ty * 8 + i;
        const int col = bcol + tx * 8;
        if (bias) {
            const u64t* bp = (const u64t*)(bias + col);
#pragma unroll
            for (int j = 0; j < 4; j++)
                asm("add.rn.f32x2 %0, %0, %1;" : "+l"(acc2[i][j]) : "l"(bp[j]));
        }
        ulonglong2 o0 = {acc2[i][0], acc2[i][1]};
        ulonglong2 o1 = {acc2[i][2], acc2[i][3]};
        *(ulonglong2*)(C + (size_t)row * N + col)     = o0;
        *(ulonglong2*)(C + (size_t)row * N + col + 4) = o1;
    }
}

// Multi-task GEMM: up to 4 independent NT GEMMs in one launch.
__global__ void __launch_bounds__(64)
gemm4(GT t0, GT t1, GT t2, GT t3, int e0, int e1, int e2)
{
    const int bx = blockIdx.x;
    GT t; int local;
    if (bx < e0)      { t = t0; local = bx; }
    else if (bx < e1) { t = t1; local = bx - e0; }
    else if (bx < e2) { t = t2; local = bx - e1; }
    else              { t = t3; local = bx - e2; }
    const int tileY = local / t.tilesX;
    const int tileX = local % t.tilesX;
    gemm_body(t.A, t.B, t.C, t.N, t.K, t.bias, tileX, tileY);
}

// ---------------- transpose Wqp [512,320] -> WqpT [320,512] -----------------
__global__ __launch_bounds__(256)
void transpose_kernel(const float* __restrict__ src, float* __restrict__ dst)
{
    __shared__ float tile[32][33];
    const int bx = blockIdx.x;   // along 320 (10 tiles)
    const int by = blockIdx.y;   // along 512 (16 tiles)
    const int txx = threadIdx.x; // 0..31
    const int tyy = threadIdx.y; // 0..7
    const int x  = bx * 32 + txx;        // src col (qd)
    const int y0 = by * 32 + tyy;        // src row (d)
#pragma unroll
    for (int i = 0; i < 32; i += 8)
        tile[tyy + i][txx] = src[(size_t)(y0 + i) * QDIM + x];
    __syncthreads();
    const int dx  = by * 32 + txx;       // dst col (d)
    const int dy0 = bx * 32 + tyy;       // dst row (qd)
#pragma unroll
    for (int i = 0; i < 32; i += 8)
        dst[(size_t)(dy0 + i) * DDIM + dx] = tile[txx][tyy + i];
}

// ---------------- L2 normalize memory slots (keys & values) ----------------
__global__ __launch_bounds__(256)
void l2norm_kernel(const float* __restrict__ keys, const float* __restrict__ vals)
{
    __shared__ float sbuf[8];
    const int row = blockIdx.x;
    const float* src = (blockIdx.y == 0) ? keys : vals;
    float* dst = (blockIdx.y == 0) ? g_keysN : g_valsN;
    const int t = threadIdx.x;

    float2 v = *(const float2*)(src + (size_t)row * DDIM + t * 2);
    float ss = v.x * v.x + v.y * v.y;
#pragma unroll
    for (int off = 16; off; off >>= 1) ss += __shfl_xor_sync(0xffffffffu, ss, off);
    if ((t & 31) == 0) sbuf[t >> 5] = ss;
    __syncthreads();
    float tot = 0.f;
#pragma unroll
    for (int w = 0; w < 8; w++) tot += sbuf[w];
    float inv = 1.0f / sqrtf(tot + 1e-12f);
    float2 o = make_float2(v.x * inv, v.y * inv);
    *(float2*)(dst + (size_t)row * DDIM + t * 2) = o;
}

// ============================================================================
// Fused top-32 (exact 4-pass radix select) + gathered multi-head attention.
// ============================================================================
__device__ __forceinline__ u32t f2ord(float f) {
    u32t b = __float_as_uint(f);
    return (b & 0x80000000u) ? ~b : (b | 0x80000000u);
}

__global__ __launch_bounds__(256)
void topk_attn_kernel(const float* __restrict__ scores,
                      const float* __restrict__ qh,
                      float* __restrict__ ctx)
{
    __shared__ u32t  s_hist[256];
    __shared__ u32t  s_suf[257];
    __shared__ int   s_idx[KSEL];
    __shared__ int   s_tie[KSEL];
    __shared__ int   s_cnt[2];
    __shared__ int   s_T;
    __shared__ float s_q[DDIM];
    __shared__ float s_dot[NHEAD][KSEL];

    const int row = blockIdx.x;
    const int t = threadIdx.x;
    const int lane = t & 31;
    const int wrp = t >> 5;

    u32t u[4];
#pragma unroll
    for (int j = 0; j < 4; j++)
        u[j] = f2ord(scores[(size_t)row * SSLOTS + t + j * 256]);
    s_q[t]       = qh[(size_t)row * DDIM + t];
    s_q[t + 256] = qh[(size_t)row * DDIM + t + 256];
    if (t < 2) s_cnt[t] = 0;

    u32t prefix = 0;
    int  need   = KSEL;

#pragma unroll
    for (int b = 3; b >= 0; b--) {
        const int sh = b * 8;
        s_hist[t] = 0;
        __syncthreads();
#pragma unroll
        for (int j = 0; j < 4; j++) {
            bool in = (b == 3) || ((u[j] >> (sh + 8)) == prefix);
            if (in) atomicAdd(&s_hist[(u[j] >> sh) & 255u], 1u);
        }
        __syncthreads();
        {
            u32t v = s_hist[t];
#pragma unroll
            for (int off = 1; off < 32; off <<= 1) {
                u32t o = __shfl_down_sync(0xffffffffu, v, off);
                if (lane + off < 32) v += o;
            }
            __shared__ u32t wsum[8];
            if (lane == 0) wsum[wrp] = v;
            __syncthreads();
            u32t woff = 0;
#pragma unroll
            for (int w = 0; w < 8; w++) woff += (w > wrp) ? wsum[w] : 0u;
            s_suf[t] = v + woff;
            if (t == 0) s_suf[256] = 0;
        }
        __syncthreads();
        if (s_suf[t] >= (u32t)need && s_suf[t + 1] < (u32t)need) s_T = t;
        __syncthreads();
        const int T = s_T;
        need -= (int)s_suf[T + 1];
        prefix = (prefix << 8) | (u32t)T;
        __syncthreads();
    }
    const u32t V = prefix;

#pragma unroll
    for (int j = 0; j < 4; j++) {
        if (u[j] > V) {
            int p = atomicAdd(&s_cnt[0], 1);
            s_idx[p] = t + j * 256;
        } else if (u[j] == V) {
            int p = atomicAdd(&s_cnt[1], 1);
            if (p < KSEL) s_tie[p] = t + j * 256;
        }
    }
    __syncthreads();
    if (t == 0) {
        int nt = min(s_cnt[1], KSEL);
        int base = s_cnt[0];
        for (int r = 0; r < need; r++) {
            int best = 1 << 30, bj = -1;
            for (int j = 0; j < nt; j++)
                if (s_tie[j] < best) { best = s_tie[j]; bj = j; }
            s_idx[base + r] = best;
            s_tie[bj] = 1 << 30;
        }
    }
    __syncthreads();

    // ---- attention: warp = head; coalesced cooperative dots ----
    const int h  = wrp;
    const int g  = lane >> 4;
    const int gl = lane & 15;

    const int myidx = s_idx[lane];

    float4 qv = *(const float4*)&s_q[h * DHEAD + gl * 4];

#pragma unroll
    for (int i = 0; i < 16; i++) {
        const int slot = i * 2 + g;
        const int rowi = __shfl_sync(0xffffffffu, myidx, slot);
        float4 kv = *(const float4*)(g_Kp + (size_t)rowi * DDIM + h * DHEAD + gl * 4);
        float p = qv.x * kv.x + qv.y * kv.y + qv.z * kv.z + qv.w * kv.w;
        p += __shfl_xor_sync(0xffffffffu, p, 8);
        p += __shfl_xor_sync(0xffffffffu, p, 4);
        p += __shfl_xor_sync(0xffffffffu, p, 2);
        p += __shfl_xor_sync(0xffffffffu, p, 1);
        if (gl == 0) s_dot[h][slot] = p;
    }
    __syncwarp();

    float dot = s_dot[h][lane] * 0.125f;
    float m = dot;
#pragma unroll
    for (int off = 16; off; off >>= 1) m = fmaxf(m, __shfl_xor_sync(0xffffffffu, m, off));
    float e = expf(dot - m);
    float s = e;
#pragma unroll
    for (int off = 16; off; off >>= 1) s += __shfl_xor_sync(0xffffffffu, s, off);
    const float myw = e / s;

    {
        const int d2 = t * 2;
        float2 acc = make_float2(0.f, 0.f);
#pragma unroll 8
        for (int kk = 0; kk < KSEL; kk++) {
            const float wv = __shfl_sync(0xffffffffu, myw, kk);
            const int rk = __shfl_sync(0xffffffffu, myidx, kk);
            float2 v = *(const float2*)(g_Vp + (size_t)rk * DDIM + d2);
            acc.x = fmaf(wv, v.x, acc.x);
            acc.y = fmaf(wv, v.y, acc.y);
        }
        *(float2*)(ctx + (size_t)row * DDIM + d2) = acc;
    }
}

// ---------------- LayerNorm over D=512 -------------------------------------
__global__ __launch_bounds__(256)
void ln_kernel(const float* __restrict__ x, const float* __restrict__ g,
               const float* __restrict__ b, float* __restrict__ y)
{
    __shared__ float sbuf[8];
    __shared__ float sbuf2[8];
    const int row = blockIdx.x;
    const int t = threadIdx.x;

    float2 v = *(const float2*)(x + (size_t)row * DDIM + t * 2);
    float s = v.x + v.y;
#pragma unroll
    for (int off = 16; off; off >>= 1) s += __shfl_xor_sync(0xffffffffu, s, off);
    if ((t & 31) == 0) sbuf[t >> 5] = s;
    __syncthreads();
    float tot = 0.f;
#pragma unroll
    for (int w = 0; w < 8; w++) tot += sbuf[w];
    float mu = tot * (1.0f / DDIM);

    float dx = v.x - mu, dy = v.y - mu;
    float ss = dx * dx + dy * dy;
#pragma unroll
    for (int off = 16; off; off >>= 1) ss += __shfl_xor_sync(0xffffffffu, ss, off);
    if ((t & 31) == 0) sbuf2[t >> 5] = ss;
    __syncthreads();
    float vs = 0.f;
#pragma unroll
    for (int w = 0; w < 8; w++) vs += sbuf2[w];
    float rstd = 1.0f / sqrtf(vs * (1.0f / DDIM) + 1e-5f);

    float2 o;
    o.x = dx * rstd * g[t * 2 + 0] + b[t * 2 + 0];
    o.y = dy * rstd * g[t * 2 + 1] + b[t * 2 + 1];
    *(float2*)(y + (size_t)row * DDIM + t * 2) = o;
}

// ---------------- launch ----------------------------------------------------
extern "C" void kernel_launch(void* const* d_in, const int* in_sizes, int n_in,
                              void* d_out, int out_size)
{
    const float* query = (const float*)d_in[0];
    const float* Wqp   = (const float*)d_in[1];
    const float* mkeys = (const float*)d_in[2];
    const float* mvals = (const float*)d_in[3];
    const float* Wq    = (const float*)d_in[4];
    const float* Wk    = (const float*)d_in[5];
    const float* Wv    = (const float*)d_in[6];
    const float* Wo    = (const float*)d_in[7];
    const float* ln_g  = (const float*)d_in[8];
    const float* ln_b  = (const float*)d_in[9];
    const float* Wout  = (const float*)d_in[10];
    const float* bout  = (const float*)d_in[11];
    float* out = (float*)d_out;

    float *q, *keysN, *valsN, *Kp, *Vp, *qh, *scores, *ctx, *ctxo, *normed;
    float *WqpT, *Wqq;
    cudaGetSymbolAddress((void**)&q,      g_q);
    cudaGetSymbolAddress((void**)&keysN,  g_keysN);
    cudaGetSymbolAddress((void**)&valsN,  g_valsN);
    cudaGetSymbolAddress((void**)&Kp,     g_Kp);
    cudaGetSymbolAddress((void**)&Vp,     g_Vp);
    cudaGetSymbolAddress((void**)&qh,     g_qh);
    cudaGetSymbolAddress((void**)&scores, g_scores);
    cudaGetSymbolAddress((void**)&ctx,    g_ctx);
    cudaGetSymbolAddress((void**)&ctxo,   g_ctxo);
    cudaGetSymbolAddress((void**)&normed, g_normed);
    cudaGetSymbolAddress((void**)&WqpT,   g_WqpT);
    cudaGetSymbolAddress((void**)&Wqq,    g_Wqq);

    // 1) normalize slot tables; transpose Wqp
    l2norm_kernel<<<dim3(SSLOTS, 2), 256>>>(mkeys, mvals);
    transpose_kernel<<<dim3(QDIM / 32, DDIM / 32), dim3(32, 8)>>>(Wqp, WqpT);

    // 2) all projections in ONE launch (808 blocks @ 64 thr):
    //    q    = query @ Wqp^T        [4096,512] K=320   512 tiles
    //    Wqq  = Wq @ WqpT^T          [512,320]  K=512    40 tiles
    //    Kp   = keysN @ Wk^T         [1024,512] K=512   128 tiles
    //    Vp   = valsN @ Wv^T         [1024,512] K=512   128 tiles
    {
        GT tq   = {query, Wqp,  q,   DDIM, QDIM, nullptr, DDIM / BN};
        GT twqq = {Wq,    WqpT, Wqq, QDIM, DDIM, nullptr, QDIM / BN};
        GT tkp  = {keysN, Wk,   Kp,  DDIM, DDIM, nullptr, DDIM / BN};
        GT tvp  = {valsN, Wv,   Vp,  DDIM, DDIM, nullptr, DDIM / BN};
        gemm4<<<512 + 40 + 128 + 128, 64>>>(tq, twqq, tkp, tvp, 512, 552, 680);
    }

    // 3) scores = q @ keysN^T [4096,1024] (1024 tiles) +
    //    qh = query @ Wqq^T   [4096,512] K=320 (512 tiles)  — one launch
    {
        GT tsc = {q,     keysN, scores, SSLOTS, DDIM, nullptr, SSLOTS / BN};
        GT tqh = {query, Wqq,   qh,     DDIM,   QDIM, nullptr, DDIM / BN};
        GT dmy = tqh;
        gemm4<<<1024 + 512, 64>>>(tsc, tqh, dmy, dmy, 1024, 1536, 1536);
    }

    // 4) fused radix-select top-32 + attention -> ctx [4096,512]
    topk_attn_kernel<<<TOKS, 256>>>(scores, qh, ctx);

    // 5) ctxo = ctx @ Wo^T (512 tiles)
    {
        GT two = {ctx, Wo, ctxo, DDIM, DDIM, nullptr, DDIM / BN};
        gemm4<<<512, 64>>>(two, two, two, two, 512, 512, 512);
    }

    // 6) LayerNorm
    ln_kernel<<<TOKS, 256>>>(ctxo, ln_g, ln_b, normed);

    // 7) out = normed @ Wout^T + bout [4096,320] (320 tiles)
    {
        GT tout = {normed, Wout, out, QDIM, DDIM, bout, QDIM / BN};
        gemm4<<<320, 64>>>(tout, tout, tout, tout, 320, 320, 320);
    }
}

// round 7
// speedup vs baseline: 2.2815x; 1.4405x over previous
#include <cuda_runtime.h>
#include <math.h>

// Problem constants
#define TOKS   4096   // B*N
#define DDIM   512
#define SSLOTS 1024
#define QDIM   320
#define KSEL   32
#define NHEAD  8
#define DHEAD  64

typedef unsigned long long u64t;
typedef unsigned int u32t;

// ---------------- scratch (device globals; no allocation allowed) ----------
__device__ float g_keysN[SSLOTS * DDIM];
__device__ float g_valsN[SSLOTS * DDIM];
__device__ float g_Kp[SSLOTS * DDIM];
__device__ float g_Vp[SSLOTS * DDIM];
__device__ float g_qh[TOKS * DDIM];
__device__ float g_scores[TOKS * SSLOTS];
__device__ float g_ctx[TOKS * DDIM];
__device__ float g_ctxo[TOKS * DDIM];
__device__ float g_normed[TOKS * DDIM];
__device__ float g_WqpT[QDIM * DDIM];   // Wqp transposed [320,512]
__device__ float g_Wqq[DDIM * QDIM];    // Wq @ Wqp       [512,320]
__device__ float g_M[SSLOTS * QDIM];    // keysN @ Wqp    [1024,320]

struct GT {
    const float* A;
    const float* B;
    float*       C;
    int N, K;
    const float* bias;
    int tilesX;   // N / 64
};

// ============================================================================
// fp32 GEMM NT (f32x2): 64x64 tile, 64 threads, 8x8 micro-tile. Used for the
// top-k-critical path (M, Wqq, scores) where fp32 accuracy is required.
// ============================================================================
#define BM 64
#define BN 64
#define BK 16
#define NTH 64
#define AF4 4
#define BF4 4

__device__ __forceinline__ void gemm_body(
    const float* __restrict__ A, const float* __restrict__ B,
    float* __restrict__ C, int N, int K, const float* __restrict__ bias,
    int tileX, int tileY)
{
    constexpr int PAD = 4;
    __shared__ float As[2][BK][BM + PAD];
    __shared__ float Bs[2][BK][BN + PAD];

    const int tid  = threadIdx.x;
    const int tx   = tid & 7;
    const int ty   = tid >> 3;
    const int brow = tileY * BM;
    const int bcol = tileX * BN;

    float4 pa[AF4], pb[BF4];

    auto loadA = [&](int k0) {
#pragma unroll
        for (int i = 0; i < AF4; i++) {
            int slot = tid + i * NTH;
            int m = slot >> 2, kq = slot & 3;
            pa[i] = *(const float4*)(A + (size_t)(brow + m) * K + k0 + kq * 4);
        }
    };
    auto loadB = [&](int k0) {
#pragma unroll
        for (int i = 0; i < BF4; i++) {
            int slot = tid + i * NTH;
            int n = slot >> 2, kq = slot & 3;
            pb[i] = *(const float4*)(B + (size_t)(bcol + n) * K + k0 + kq * 4);
        }
    };
    auto storeA = [&](int buf) {
#pragma unroll
        for (int i = 0; i < AF4; i++) {
            int slot = tid + i * NTH;
            int m = slot >> 2, kq = slot & 3;
            As[buf][kq * 4 + 0][m] = pa[i].x;
            As[buf][kq * 4 + 1][m] = pa[i].y;
            As[buf][kq * 4 + 2][m] = pa[i].z;
            As[buf][kq * 4 + 3][m] = pa[i].w;
        }
    };
    auto storeB = [&](int buf) {
#pragma unroll
        for (int i = 0; i < BF4; i++) {
            int slot = tid + i * NTH;
            int n = slot >> 2, kq = slot & 3;
            Bs[buf][kq * 4 + 0][n] = pb[i].x;
            Bs[buf][kq * 4 + 1][n] = pb[i].y;
            Bs[buf][kq * 4 + 2][n] = pb[i].z;
            Bs[buf][kq * 4 + 3][n] = pb[i].w;
        }
    };

    u64t acc2[8][4];
#pragma unroll
    for (int i = 0; i < 8; i++)
#pragma unroll
        for (int j = 0; j < 4; j++) acc2[i][j] = 0ull;

    const int ntiles = K / BK;
    loadA(0); loadB(0);
    storeA(0); storeB(0);
    __syncthreads();

    for (int t = 0; t < ntiles; t++) {
        const int cur = t & 1;
        const bool more = (t + 1 < ntiles);
        if (more) { loadA((t + 1) * BK); loadB((t + 1) * BK); }

#pragma unroll
        for (int kk = 0; kk < BK; kk++) {
            float4 a0 = *(const float4*)&As[cur][kk][ty * 8];
            float4 a1 = *(const float4*)&As[cur][kk][ty * 8 + 4];
            ulonglong2 bq0 = *(const ulonglong2*)&Bs[cur][kk][tx * 8];
            ulonglong2 bq1 = *(const ulonglong2*)&Bs[cur][kk][tx * 8 + 4];
            u64t bb[4] = {bq0.x, bq0.y, bq1.x, bq1.y};
            float av[8] = {a0.x, a0.y, a0.z, a0.w, a1.x, a1.y, a1.z, a1.w};
#pragma unroll
            for (int i = 0; i < 8; i++) {
                u64t ad;
                asm("mov.b64 %0, {%1, %1};" : "=l"(ad) : "f"(av[i]));
#pragma unroll
                for (int j = 0; j < 4; j++)
                    asm("fma.rn.f32x2 %0, %1, %2, %0;"
                        : "+l"(acc2[i][j]) : "l"(ad), "l"(bb[j]));
            }
        }
        if (more) { storeA(cur ^ 1); storeB(cur ^ 1); }
        __syncthreads();
    }

#pragma unroll
    for (int i = 0; i < 8; i++) {
        const int row = brow + ty * 8 + i;
        const int col = bcol + tx * 8;
        if (bias) {
            const u64t* bp = (const u64t*)(bias + col);
#pragma unroll
            for (int j = 0; j < 4; j++)
                asm("add.rn.f32x2 %0, %0, %1;" : "+l"(acc2[i][j]) : "l"(bp[j]));
        }
        ulonglong2 o0 = {acc2[i][0], acc2[i][1]};
        ulonglong2 o1 = {acc2[i][2], acc2[i][3]};
        *(ulonglong2*)(C + (size_t)row * N + col)     = o0;
        *(ulonglong2*)(C + (size_t)row * N + col + 4) = o1;
    }
}

__global__ void __launch_bounds__(64)
gemm4(GT t0, GT t1, GT t2, GT t3, int e0, int e1, int e2)
{
    const int bx = blockIdx.x;
    GT t; int local;
    if (bx < e0)      { t = t0; local = bx; }
    else if (bx < e1) { t = t1; local = bx - e0; }
    else if (bx < e2) { t = t2; local = bx - e1; }
    else              { t = t3; local = bx - e2; }
    gemm_body(t.A, t.B, t.C, t.N, t.K, t.bias, local % t.tilesX, local / t.tilesX);
}

// ============================================================================
// tf32 tensor-core GEMM NT: 64x64 tile, 128 threads (4 warps, 2x2 grid of
// 32x32 warp tiles), mma.sync.m16n8k8 tf32 with rna rounding at smem store.
// ============================================================================
#define TBK 16

__device__ __forceinline__ u32t cvt_tf32(float x) {
    u32t r;
    asm("cvt.rna.tf32.f32 %0, %1;" : "=r"(r) : "f"(x));
    return r;
}

#define MMA_TF32(d, a, b)                                                     \
    asm volatile("mma.sync.aligned.m16n8k8.row.col.f32.tf32.tf32.f32 "       \
                 "{%0,%1,%2,%3}, {%4,%5,%6,%7}, {%8,%9}, {%0,%1,%2,%3};"     \
                 : "+f"(d[0]), "+f"(d[1]), "+f"(d[2]), "+f"(d[3])            \
                 : "r"(a[0]), "r"(a[1]), "r"(a[2]), "r"(a[3]),               \
                   "r"(b[0]), "r"(b[1]))

__device__ __forceinline__ void gemm_tf32_body(
    const float* __restrict__ A, const float* __restrict__ B,
    float* __restrict__ C, int N, int K, const float* __restrict__ bias,
    int tileX, int tileY)
{
    // [m][k] / [n][k] layout, stride 20 words: conflict-free fragment loads
    __shared__ u32t As[2][64][TBK + 4];
    __shared__ u32t Bs[2][64][TBK + 4];

    const int tid  = threadIdx.x;
    const int warp = tid >> 5;
    const int lane = tid & 31;
    const int g    = lane >> 2;   // groupID
    const int tg   = lane & 3;    // thread in group
    const int wm   = (warp >> 1) * 32;
    const int wn   = (warp & 1) * 32;
    const int brow = tileY * 64;
    const int bcol = tileX * 64;

    float4 pa[2], pb[2];

    auto loadA = [&](int k0) {
#pragma unroll
        for (int i = 0; i < 2; i++) {
            int slot = tid + i * 128;
            int row = slot >> 2, kq = slot & 3;
            pa[i] = *(const float4*)(A + (size_t)(brow + row) * K + k0 + kq * 4);
        }
    };
    auto loadB = [&](int k0) {
#pragma unroll
        for (int i = 0; i < 2; i++) {
            int slot = tid + i * 128;
            int row = slot >> 2, kq = slot & 3;
            pb[i] = *(const float4*)(B + (size_t)(bcol + row) * K + k0 + kq * 4);
        }
    };
    auto storeA = [&](int buf) {
#pragma unroll
        for (int i = 0; i < 2; i++) {
            int slot = tid + i * 128;
            int row = slot >> 2, kq = slot & 3;
            uint4 q = {cvt_tf32(pa[i].x), cvt_tf32(pa[i].y),
                       cvt_tf32(pa[i].z), cvt_tf32(pa[i].w)};
            *(uint4*)&As[buf][row][kq * 4] = q;
        }
    };
    auto storeB = [&](int buf) {
#pragma unroll
        for (int i = 0; i < 2; i++) {
            int slot = tid + i * 128;
            int row = slot >> 2, kq = slot & 3;
            uint4 q = {cvt_tf32(pb[i].x), cvt_tf32(pb[i].y),
                       cvt_tf32(pb[i].z), cvt_tf32(pb[i].w)};
            *(uint4*)&Bs[buf][row][kq * 4] = q;
        }
    };

    float acc[2][4][4];
#pragma unroll
    for (int mi = 0; mi < 2; mi++)
#pragma unroll
        for (int ni = 0; ni < 4; ni++)
#pragma unroll
            for (int r = 0; r < 4; r++) acc[mi][ni][r] = 0.f;

    const int ntiles = K / TBK;
    loadA(0); loadB(0);
    storeA(0); storeB(0);
    __syncthreads();

    for (int t = 0; t < ntiles; t++) {
        const int cur = t & 1;
        const bool more = (t + 1 < ntiles);
        if (more) { loadA((t + 1) * TBK); loadB((t + 1) * TBK); }

#pragma unroll
        for (int ks = 0; ks < 2; ks++) {
            const int kb = ks * 8;
            u32t a[2][4], b[4][2];
#pragma unroll
            for (int mi = 0; mi < 2; mi++) {
                a[mi][0] = As[cur][wm + mi * 16 + g][kb + tg];
                a[mi][1] = As[cur][wm + mi * 16 + g + 8][kb + tg];
                a[mi][2] = As[cur][wm + mi * 16 + g][kb + tg + 4];
                a[mi][3] = As[cur][wm + mi * 16 + g + 8][kb + tg + 4];
            }
#pragma unroll
            for (int ni = 0; ni < 4; ni++) {
                b[ni][0] = Bs[cur][wn + ni * 8 + g][kb + tg];
                b[ni][1] = Bs[cur][wn + ni * 8 + g][kb + tg + 4];
            }
#pragma unroll
            for (int mi = 0; mi < 2; mi++)
#pragma unroll
                for (int ni = 0; ni < 4; ni++)
                    MMA_TF32(acc[mi][ni], a[mi], b[ni]);
        }
        if (more) { storeA(cur ^ 1); storeB(cur ^ 1); }
        __syncthreads();
    }

#pragma unroll
    for (int mi = 0; mi < 2; mi++) {
        const int r0 = brow + wm + mi * 16 + g;
#pragma unroll
        for (int ni = 0; ni < 4; ni++) {
            const int c = bcol + wn + ni * 8 + 2 * tg;
            float b0 = 0.f, b1 = 0.f;
            if (bias) { b0 = bias[c]; b1 = bias[c + 1]; }
            float2 o0 = make_float2(acc[mi][ni][0] + b0, acc[mi][ni][1] + b1);
            float2 o1 = make_float2(acc[mi][ni][2] + b0, acc[mi][ni][3] + b1);
            *(float2*)(C + (size_t)r0 * N + c)       = o0;
            *(float2*)(C + (size_t)(r0 + 8) * N + c) = o1;
        }
    }
}

__global__ void __launch_bounds__(128)
gemm4t(GT t0, GT t1, GT t2, GT t3, int e0, int e1, int e2)
{
    const int bx = blockIdx.x;
    GT t; int local;
    if (bx < e0)      { t = t0; local = bx; }
    else if (bx < e1) { t = t1; local = bx - e0; }
    else if (bx < e2) { t = t2; local = bx - e1; }
    else              { t = t3; local = bx - e2; }
    gemm_tf32_body(t.A, t.B, t.C, t.N, t.K, t.bias, local % t.tilesX, local / t.tilesX);
}

// ---------------- transpose Wqp [512,320] -> WqpT [320,512] -----------------
__global__ __launch_bounds__(256)
void transpose_kernel(const float* __restrict__ src, float* __restrict__ dst)
{
    __shared__ float tile[32][33];
    const int bx = blockIdx.x;
    const int by = blockIdx.y;
    const int txx = threadIdx.x;
    const int tyy = threadIdx.y;
    const int x  = bx * 32 + txx;
    const int y0 = by * 32 + tyy;
#pragma unroll
    for (int i = 0; i < 32; i += 8)
        tile[tyy + i][txx] = src[(size_t)(y0 + i) * QDIM + x];
    __syncthreads();
    const int dx  = by * 32 + txx;
    const int dy0 = bx * 32 + tyy;
#pragma unroll
    for (int i = 0; i < 32; i += 8)
        dst[(size_t)(dy0 + i) * DDIM + dx] = tile[txx][tyy + i];
}

// ---------------- L2 normalize memory slots (keys & values) ----------------
__global__ __launch_bounds__(256)
void l2norm_kernel(const float* __restrict__ keys, const float* __restrict__ vals)
{
    __shared__ float sbuf[8];
    const int row = blockIdx.x;
    const float* src = (blockIdx.y == 0) ? keys : vals;
    float* dst = (blockIdx.y == 0) ? g_keysN : g_valsN;
    const int t = threadIdx.x;

    float2 v = *(const float2*)(src + (size_t)row * DDIM + t * 2);
    float ss = v.x * v.x + v.y * v.y;
#pragma unroll
    for (int off = 16; off; off >>= 1) ss += __shfl_xor_sync(0xffffffffu, ss, off);
    if ((t & 31) == 0) sbuf[t >> 5] = ss;
    __syncthreads();
    float tot = 0.f;
#pragma unroll
    for (int w = 0; w < 8; w++) tot += sbuf[w];
    float inv = 1.0f / sqrtf(tot + 1e-12f);
    float2 o = make_float2(v.x * inv, v.y * inv);
    *(float2*)(dst + (size_t)row * DDIM + t * 2) = o;
}

// ============================================================================
// Fused top-32 (exact 4-pass radix select) + gathered multi-head attention.
// ============================================================================
__device__ __forceinline__ u32t f2ord(float f) {
    u32t b = __float_as_uint(f);
    return (b & 0x80000000u) ? ~b : (b | 0x80000000u);
}

__global__ __launch_bounds__(256)
void topk_attn_kernel(const float* __restrict__ scores,
                      const float* __restrict__ qh,
                      float* __restrict__ ctx)
{
    __shared__ u32t  s_hist[256];
    __shared__ u32t  s_suf[257];
    __shared__ int   s_idx[KSEL];
    __shared__ int   s_tie[KSEL];
    __shared__ int   s_cnt[2];
    __shared__ int   s_T;
    __shared__ float s_q[DDIM];
    __shared__ float s_dot[NHEAD][KSEL];

    const int row = blockIdx.x;
    const int t = threadIdx.x;
    const int lane = t & 31;
    const int wrp = t >> 5;

    u32t u[4];
#pragma unroll
    for (int j = 0; j < 4; j++)
        u[j] = f2ord(scores[(size_t)row * SSLOTS + t + j * 256]);
    s_q[t]       = qh[(size_t)row * DDIM + t];
    s_q[t + 256] = qh[(size_t)row * DDIM + t + 256];
    if (t < 2) s_cnt[t] = 0;

    u32t prefix = 0;
    int  need   = KSEL;

#pragma unroll
    for (int b = 3; b >= 0; b--) {
        const int sh = b * 8;
        s_hist[t] = 0;
        __syncthreads();
#pragma unroll
        for (int j = 0; j < 4; j++) {
            bool in = (b == 3) || ((u[j] >> (sh + 8)) == prefix);
            if (in) atomicAdd(&s_hist[(u[j] >> sh) & 255u], 1u);
        }
        __syncthreads();
        {
            u32t v = s_hist[t];
#pragma unroll
            for (int off = 1; off < 32; off <<= 1) {
                u32t o = __shfl_down_sync(0xffffffffu, v, off);
                if (lane + off < 32) v += o;
            }
            __shared__ u32t wsum[8];
            if (lane == 0) wsum[wrp] = v;
            __syncthreads();
            u32t woff = 0;
#pragma unroll
            for (int w = 0; w < 8; w++) woff += (w > wrp) ? wsum[w] : 0u;
            s_suf[t] = v + woff;
            if (t == 0) s_suf[256] = 0;
        }
        __syncthreads();
        if (s_suf[t] >= (u32t)need && s_suf[t + 1] < (u32t)need) s_T = t;
        __syncthreads();
        const int T = s_T;
        need -= (int)s_suf[T + 1];
        prefix = (prefix << 8) | (u32t)T;
        __syncthreads();
    }
    const u32t V = prefix;

#pragma unroll
    for (int j = 0; j < 4; j++) {
        if (u[j] > V) {
            int p = atomicAdd(&s_cnt[0], 1);
            s_idx[p] = t + j * 256;
        } else if (u[j] == V) {
            int p = atomicAdd(&s_cnt[1], 1);
            if (p < KSEL) s_tie[p] = t + j * 256;
        }
    }
    __syncthreads();
    if (t == 0) {
        int nt = min(s_cnt[1], KSEL);
        int base = s_cnt[0];
        for (int r = 0; r < need; r++) {
            int best = 1 << 30, bj = -1;
            for (int j = 0; j < nt; j++)
                if (s_tie[j] < best) { best = s_tie[j]; bj = j; }
            s_idx[base + r] = best;
            s_tie[bj] = 1 << 30;
        }
    }
    __syncthreads();

    // ---- attention: warp = head; coalesced cooperative dots ----
    const int h  = wrp;
    const int g  = lane >> 4;
    const int gl = lane & 15;

    const int myidx = s_idx[lane];

    float4 qv = *(const float4*)&s_q[h * DHEAD + gl * 4];

#pragma unroll
    for (int i = 0; i < 16; i++) {
        const int slot = i * 2 + g;
        const int rowi = __shfl_sync(0xffffffffu, myidx, slot);
        float4 kv = *(const float4*)(g_Kp + (size_t)rowi * DDIM + h * DHEAD + gl * 4);
        float p = qv.x * kv.x + qv.y * kv.y + qv.z * kv.z + qv.w * kv.w;
        p += __shfl_xor_sync(0xffffffffu, p, 8);
        p += __shfl_xor_sync(0xffffffffu, p, 4);
        p += __shfl_xor_sync(0xffffffffu, p, 2);
        p += __shfl_xor_sync(0xffffffffu, p, 1);
        if (gl == 0) s_dot[h][slot] = p;
    }
    __syncwarp();

    float dot = s_dot[h][lane] * 0.125f;
    float m = dot;
#pragma unroll
    for (int off = 16; off; off >>= 1) m = fmaxf(m, __shfl_xor_sync(0xffffffffu, m, off));
    float e = expf(dot - m);
    float s = e;
#pragma unroll
    for (int off = 16; off; off >>= 1) s += __shfl_xor_sync(0xffffffffu, s, off);
    const float myw = e / s;

    {
        const int d2 = t * 2;
        float2 acc = make_float2(0.f, 0.f);
#pragma unroll 8
        for (int kk = 0; kk < KSEL; kk++) {
            const float wv = __shfl_sync(0xffffffffu, myw, kk);
            const int rk = __shfl_sync(0xffffffffu, myidx, kk);
            float2 v = *(const float2*)(g_Vp + (size_t)rk * DDIM + d2);
            acc.x = fmaf(wv, v.x, acc.x);
            acc.y = fmaf(wv, v.y, acc.y);
        }
        *(float2*)(ctx + (size_t)row * DDIM + d2) = acc;
    }
}

// ---------------- LayerNorm over D=512 -------------------------------------
__global__ __launch_bounds__(256)
void ln_kernel(const float* __restrict__ x, const float* __restrict__ g,
               const float* __restrict__ b, float* __restrict__ y)
{
    __shared__ float sbuf[8];
    __shared__ float sbuf2[8];
    const int row = blockIdx.x;
    const int t = threadIdx.x;

    float2 v = *(const float2*)(x + (size_t)row * DDIM + t * 2);
    float s = v.x + v.y;
#pragma unroll
    for (int off = 16; off; off >>= 1) s += __shfl_xor_sync(0xffffffffu, s, off);
    if ((t & 31) == 0) sbuf[t >> 5] = s;
    __syncthreads();
    float tot = 0.f;
#pragma unroll
    for (int w = 0; w < 8; w++) tot += sbuf[w];
    float mu = tot * (1.0f / DDIM);

    float dx = v.x - mu, dy = v.y - mu;
    float ss = dx * dx + dy * dy;
#pragma unroll
    for (int off = 16; off; off >>= 1) ss += __shfl_xor_sync(0xffffffffu, ss, off);
    if ((t & 31) == 0) sbuf2[t >> 5] = ss;
    __syncthreads();
    float vs = 0.f;
#pragma unroll
    for (int w = 0; w < 8; w++) vs += sbuf2[w];
    float rstd = 1.0f / sqrtf(vs * (1.0f / DDIM) + 1e-5f);

    float2 o;
    o.x = dx * rstd * g[t * 2 + 0] + b[t * 2 + 0];
    o.y = dy * rstd * g[t * 2 + 1] + b[t * 2 + 1];
    *(float2*)(y + (size_t)row * DDIM + t * 2) = o;
}

// ---------------- launch ----------------------------------------------------
extern "C" void kernel_launch(void* const* d_in, const int* in_sizes, int n_in,
                              void* d_out, int out_size)
{
    const float* query = (const float*)d_in[0];
    const float* Wqp   = (const float*)d_in[1];
    const float* mkeys = (const float*)d_in[2];
    const float* mvals = (const float*)d_in[3];
    const float* Wq    = (const float*)d_in[4];
    const float* Wk    = (const float*)d_in[5];
    const float* Wv    = (const float*)d_in[6];
    const float* Wo    = (const float*)d_in[7];
    const float* ln_g  = (const float*)d_in[8];
    const float* ln_b  = (const float*)d_in[9];
    const float* Wout  = (const float*)d_in[10];
    const float* bout  = (const float*)d_in[11];
    float* out = (float*)d_out;

    float *keysN, *valsN, *Kp, *Vp, *qh, *scores, *ctx, *ctxo, *normed;
    float *WqpT, *Wqq, *M;
    cudaGetSymbolAddress((void**)&keysN,  g_keysN);
    cudaGetSymbolAddress((void**)&valsN,  g_valsN);
    cudaGetSymbolAddress((void**)&Kp,     g_Kp);
    cudaGetSymbolAddress((void**)&Vp,     g_Vp);
    cudaGetSymbolAddress((void**)&qh,     g_qh);
    cudaGetSymbolAddress((void**)&scores, g_scores);
    cudaGetSymbolAddress((void**)&ctx,    g_ctx);
    cudaGetSymbolAddress((void**)&ctxo,   g_ctxo);
    cudaGetSymbolAddress((void**)&normed, g_normed);
    cudaGetSymbolAddress((void**)&WqpT,   g_WqpT);
    cudaGetSymbolAddress((void**)&Wqq,    g_Wqq);
    cudaGetSymbolAddress((void**)&M,      g_M);

    // 1) normalize slot tables; transpose Wqp
    l2norm_kernel<<<dim3(SSLOTS, 2), 256>>>(mkeys, mvals);
    transpose_kernel<<<dim3(QDIM / 32, DDIM / 32), dim3(32, 8)>>>(Wqp, WqpT);

    // 2) fp32: M = keysN @ WqpT^T [1024,320] (80 tiles);
    //          Wqq = Wq @ WqpT^T  [512,320]  (40 tiles)
    {
        GT tm   = {keysN, WqpT, M,   QDIM, DDIM, nullptr, QDIM / BN};
        GT twqq = {Wq,    WqpT, Wqq, QDIM, DDIM, nullptr, QDIM / BN};
        GT dmy  = twqq;
        gemm4<<<80 + 40, 64>>>(tm, twqq, dmy, dmy, 80, 120, 120);
    }

    // 3) fp32: scores = query @ M^T [4096,1024], K=320 (1024 tiles)
    {
        GT tsc = {query, M, scores, SSLOTS, QDIM, nullptr, SSLOTS / BN};
        gemm4<<<1024, 64>>>(tsc, tsc, tsc, tsc, 1024, 1024, 1024);
    }

    // 4) tf32: qh = query @ Wqq^T [4096,512] K=320 (512 tiles);
    //          Kp = keysN @ Wk^T  [1024,512] (128); Vp = valsN @ Wv^T (128)
    {
        GT tqh = {query, Wqq, qh, DDIM, QDIM, nullptr, DDIM / 64};
        GT tkp = {keysN, Wk,  Kp, DDIM, DDIM, nullptr, DDIM / 64};
        GT tvp = {valsN, Wv,  Vp, DDIM, DDIM, nullptr, DDIM / 64};
        GT dmy = tvp;
        gemm4t<<<512 + 128 + 128, 128>>>(tqh, tkp, tvp, dmy, 512, 640, 768);
    }

    // 5) fused radix-select top-32 + attention -> ctx [4096,512]
    topk_attn_kernel<<<TOKS, 256>>>(scores, qh, ctx);

    // 6) tf32: ctxo = ctx @ Wo^T (512 tiles)
    {
        GT two = {ctx, Wo, ctxo, DDIM, DDIM, nullptr, DDIM / 64};
        gemm4t<<<512, 128>>>(two, two, two, two, 512, 512, 512);
    }

    // 7) LayerNorm
    ln_kernel<<<TOKS, 256>>>(ctxo, ln_g, ln_b, normed);

    // 8) tf32: out = normed @ Wout^T + bout [4096,320] (320 tiles)
    {
        GT tout = {normed, Wout, out, QDIM, DDIM, bout, QDIM / 64};
        gemm4t<<<320, 128>>>(tout, tout, tout, tout, 320, 320, 320);
    }
}

// round 8
// speedup vs baseline: 2.5384x; 1.1126x over previous
#include <cuda_runtime.h>
#include <math.h>

// Problem constants
#define TOKS   4096   // B*N
#define DDIM   512
#define SSLOTS 1024
#define QDIM   320
#define KSEL   32
#define NHEAD  8
#define DHEAD  64

typedef unsigned long long u64t;
typedef unsigned int u32t;

// ---------------- scratch (device globals; no allocation allowed) ----------
__device__ float g_keysN[SSLOTS * DDIM];
__device__ float g_valsN[SSLOTS * DDIM];
__device__ float g_Kp[SSLOTS * DDIM];
__device__ float g_Vp[SSLOTS * DDIM];
__device__ float g_qh[TOKS * DDIM];
__device__ float g_scores[TOKS * SSLOTS];
__device__ float g_ctx[TOKS * DDIM];
__device__ float g_ctxo[TOKS * DDIM];
__device__ float g_normed[TOKS * DDIM];
__device__ float g_WqpT[QDIM * DDIM];   // Wqp transposed [320,512]
__device__ float g_Wqq[DDIM * QDIM];    // Wq @ Wqp       [512,320]
__device__ float g_M[SSLOTS * QDIM];    // keysN @ Wqp    [1024,320]

struct GT {
    const float* A;
    const float* B;
    float*       C;
    int N, K;
    const float* bias;
    int tilesX;   // N / 64
    int prec3;    // 1 = 3xTF32 split-precision (fp32-class accuracy)
};

// ============================================================================
// fp32 GEMM NT (f32x2): 64x64 tile, 64 threads, 8x8 micro-tile. Used only for
// the tiny fp32 precomputes (M, Wqq).
// ============================================================================
#define BM 64
#define BN 64
#define BK 16
#define NTH 64
#define AF4 4
#define BF4 4

__device__ __forceinline__ void gemm_body(
    const float* __restrict__ A, const float* __restrict__ B,
    float* __restrict__ C, int N, int K, const float* __restrict__ bias,
    int tileX, int tileY)
{
    constexpr int PAD = 4;
    __shared__ float As[2][BK][BM + PAD];
    __shared__ float Bs[2][BK][BN + PAD];

    const int tid  = threadIdx.x;
    const int tx   = tid & 7;
    const int ty   = tid >> 3;
    const int brow = tileY * BM;
    const int bcol = tileX * BN;

    float4 pa[AF4], pb[BF4];

    auto loadA = [&](int k0) {
#pragma unroll
        for (int i = 0; i < AF4; i++) {
            int slot = tid + i * NTH;
            int m = slot >> 2, kq = slot & 3;
            pa[i] = *(const float4*)(A + (size_t)(brow + m) * K + k0 + kq * 4);
        }
    };
    auto loadB = [&](int k0) {
#pragma unroll
        for (int i = 0; i < BF4; i++) {
            int slot = tid + i * NTH;
            int n = slot >> 2, kq = slot & 3;
            pb[i] = *(const float4*)(B + (size_t)(bcol + n) * K + k0 + kq * 4);
        }
    };
    auto storeA = [&](int buf) {
#pragma unroll
        for (int i = 0; i < AF4; i++) {
            int slot = tid + i * NTH;
            int m = slot >> 2, kq = slot & 3;
            As[buf][kq * 4 + 0][m] = pa[i].x;
            As[buf][kq * 4 + 1][m] = pa[i].y;
            As[buf][kq * 4 + 2][m] = pa[i].z;
            As[buf][kq * 4 + 3][m] = pa[i].w;
        }
    };
    auto storeB = [&](int buf) {
#pragma unroll
        for (int i = 0; i < BF4; i++) {
            int slot = tid + i * NTH;
            int n = slot >> 2, kq = slot & 3;
            Bs[buf][kq * 4 + 0][n] = pb[i].x;
            Bs[buf][kq * 4 + 1][n] = pb[i].y;
            Bs[buf][kq * 4 + 2][n] = pb[i].z;
            Bs[buf][kq * 4 + 3][n] = pb[i].w;
        }
    };

    u64t acc2[8][4];
#pragma unroll
    for (int i = 0; i < 8; i++)
#pragma unroll
        for (int j = 0; j < 4; j++) acc2[i][j] = 0ull;

    const int ntiles = K / BK;
    loadA(0); loadB(0);
    storeA(0); storeB(0);
    __syncthreads();

    for (int t = 0; t < ntiles; t++) {
        const int cur = t & 1;
        const bool more = (t + 1 < ntiles);
        if (more) { loadA((t + 1) * BK); loadB((t + 1) * BK); }

#pragma unroll
        for (int kk = 0; kk < BK; kk++) {
            float4 a0 = *(const float4*)&As[cur][kk][ty * 8];
            float4 a1 = *(const float4*)&As[cur][kk][ty * 8 + 4];
            ulonglong2 bq0 = *(const ulonglong2*)&Bs[cur][kk][tx * 8];
            ulonglong2 bq1 = *(const ulonglong2*)&Bs[cur][kk][tx * 8 + 4];
            u64t bb[4] = {bq0.x, bq0.y, bq1.x, bq1.y};
            float av[8] = {a0.x, a0.y, a0.z, a0.w, a1.x, a1.y, a1.z, a1.w};
#pragma unroll
            for (int i = 0; i < 8; i++) {
                u64t ad;
                asm("mov.b64 %0, {%1, %1};" : "=l"(ad) : "f"(av[i]));
#pragma unroll
                for (int j = 0; j < 4; j++)
                    asm("fma.rn.f32x2 %0, %1, %2, %0;"
                        : "+l"(acc2[i][j]) : "l"(ad), "l"(bb[j]));
            }
        }
        if (more) { storeA(cur ^ 1); storeB(cur ^ 1); }
        __syncthreads();
    }

#pragma unroll
    for (int i = 0; i < 8; i++) {
        const int row = brow + ty * 8 + i;
        const int col = bcol + tx * 8;
        if (bias) {
            const u64t* bp = (const u64t*)(bias + col);
#pragma unroll
            for (int j = 0; j < 4; j++)
                asm("add.rn.f32x2 %0, %0, %1;" : "+l"(acc2[i][j]) : "l"(bp[j]));
        }
        ulonglong2 o0 = {acc2[i][0], acc2[i][1]};
        ulonglong2 o1 = {acc2[i][2], acc2[i][3]};
        *(ulonglong2*)(C + (size_t)row * N + col)     = o0;
        *(ulonglong2*)(C + (size_t)row * N + col + 4) = o1;
    }
}

__global__ void __launch_bounds__(64)
gemm4(GT t0, GT t1, GT t2, GT t3, int e0, int e1, int e2)
{
    const int bx = blockIdx.x;
    GT t; int local;
    if (bx < e0)      { t = t0; local = bx; }
    else if (bx < e1) { t = t1; local = bx - e0; }
    else if (bx < e2) { t = t2; local = bx - e1; }
    else              { t = t3; local = bx - e2; }
    gemm_body(t.A, t.B, t.C, t.N, t.K, t.bias, local % t.tilesX, local / t.tilesX);
}

// ============================================================================
// tf32 tensor-core GEMM NT: 64x64 tile, 128 threads (2x2 warp grid of 32x32),
// mma.sync.m16n8k8. P3=true runs the 3xTF32 split-precision scheme
// (hi*hi + hi*lo + lo*hi) giving fp32-class accuracy at tensor-core rate.
// ============================================================================
#define TBK 16
#define SSTR 20   // smem row stride (words)

__device__ __forceinline__ u32t cvt_tf32(float x) {
    u32t r;
    asm("cvt.rna.tf32.f32 %0, %1;" : "=r"(r) : "f"(x));
    return r;
}

#define MMA_TF32(d, a, b)                                                     \
    asm volatile("mma.sync.aligned.m16n8k8.row.col.f32.tf32.tf32.f32 "       \
                 "{%0,%1,%2,%3}, {%4,%5,%6,%7}, {%8,%9}, {%0,%1,%2,%3};"     \
                 : "+f"(d[0]), "+f"(d[1]), "+f"(d[2]), "+f"(d[3])            \
                 : "r"(a[0]), "r"(a[1]), "r"(a[2]), "r"(a[3]),               \
                   "r"(b[0]), "r"(b[1]))

template<bool P3>
__device__ __forceinline__ void tf32_body(
    u32t (*As)[64][SSTR], u32t (*Bs)[64][SSTR],
    u32t (*Asl)[64][SSTR], u32t (*Bsl)[64][SSTR],
    const float* __restrict__ A, const float* __restrict__ B,
    float* __restrict__ C, int N, int K, const float* __restrict__ bias,
    int tileX, int tileY)
{
    const int tid  = threadIdx.x;
    const int warp = tid >> 5;
    const int lane = tid & 31;
    const int g    = lane >> 2;
    const int tg   = lane & 3;
    const int wm   = (warp >> 1) * 32;
    const int wn   = (warp & 1) * 32;
    const int brow = tileY * 64;
    const int bcol = tileX * 64;

    float4 pa[2], pb[2];

    auto loadA = [&](int k0) {
#pragma unroll
        for (int i = 0; i < 2; i++) {
            int slot = tid + i * 128;
            int row = slot >> 2, kq = slot & 3;
            pa[i] = *(const float4*)(A + (size_t)(brow + row) * K + k0 + kq * 4);
        }
    };
    auto loadB = [&](int k0) {
#pragma unroll
        for (int i = 0; i < 2; i++) {
            int slot = tid + i * 128;
            int row = slot >> 2, kq = slot & 3;
            pb[i] = *(const float4*)(B + (size_t)(bcol + row) * K + k0 + kq * 4);
        }
    };
    auto split_store = [&](u32t (*hi)[64][SSTR], u32t (*lo)[64][SSTR],
                           int buf, float4* p) {
#pragma unroll
        for (int i = 0; i < 2; i++) {
            int slot = tid + i * 128;
            int row = slot >> 2, kq = slot & 3;
            float v[4] = {p[i].x, p[i].y, p[i].z, p[i].w};
            uint4 qh_, ql_;
            u32t* qhp = (u32t*)&qh_;
            u32t* qlp = (u32t*)&ql_;
#pragma unroll
            for (int c = 0; c < 4; c++) {
                u32t h = cvt_tf32(v[c]);
                qhp[c] = h;
                if (P3) qlp[c] = cvt_tf32(v[c] - __uint_as_float(h));
            }
            *(uint4*)&hi[buf][row][kq * 4] = qh_;
            if (P3) *(uint4*)&lo[buf][row][kq * 4] = ql_;
        }
    };

    float acc[2][4][4];
#pragma unroll
    for (int mi = 0; mi < 2; mi++)
#pragma unroll
        for (int ni = 0; ni < 4; ni++)
#pragma unroll
            for (int r = 0; r < 4; r++) acc[mi][ni][r] = 0.f;

    const int ntiles = K / TBK;
    loadA(0); loadB(0);
    split_store(As, Asl, 0, pa);
    split_store(Bs, Bsl, 0, pb);
    __syncthreads();

    for (int t = 0; t < ntiles; t++) {
        const int cur = t & 1;
        const bool more = (t + 1 < ntiles);
        if (more) { loadA((t + 1) * TBK); loadB((t + 1) * TBK); }

#pragma unroll
        for (int ks = 0; ks < 2; ks++) {
            const int kb = ks * 8;
            u32t a[2][4], b[4][2];
            u32t al[2][4], bl[4][2];
#pragma unroll
            for (int mi = 0; mi < 2; mi++) {
                a[mi][0] = As[cur][wm + mi * 16 + g][kb + tg];
                a[mi][1] = As[cur][wm + mi * 16 + g + 8][kb + tg];
                a[mi][2] = As[cur][wm + mi * 16 + g][kb + tg + 4];
                a[mi][3] = As[cur][wm + mi * 16 + g + 8][kb + tg + 4];
                if (P3) {
                    al[mi][0] = Asl[cur][wm + mi * 16 + g][kb + tg];
                    al[mi][1] = Asl[cur][wm + mi * 16 + g + 8][kb + tg];
                    al[mi][2] = Asl[cur][wm + mi * 16 + g][kb + tg + 4];
                    al[mi][3] = Asl[cur][wm + mi * 16 + g + 8][kb + tg + 4];
                }
            }
#pragma unroll
            for (int ni = 0; ni < 4; ni++) {
                b[ni][0] = Bs[cur][wn + ni * 8 + g][kb + tg];
                b[ni][1] = Bs[cur][wn + ni * 8 + g][kb + tg + 4];
                if (P3) {
                    bl[ni][0] = Bsl[cur][wn + ni * 8 + g][kb + tg];
                    bl[ni][1] = Bsl[cur][wn + ni * 8 + g][kb + tg + 4];
                }
            }
#pragma unroll
            for (int mi = 0; mi < 2; mi++)
#pragma unroll
                for (int ni = 0; ni < 4; ni++) {
                    if (P3) {
                        MMA_TF32(acc[mi][ni], a[mi], bl[ni]);   // hi*lo
                        MMA_TF32(acc[mi][ni], al[mi], b[ni]);   // lo*hi
                    }
                    MMA_TF32(acc[mi][ni], a[mi], b[ni]);        // hi*hi
                }
        }
        if (more) {
            split_store(As, Asl, cur ^ 1, pa);
            split_store(Bs, Bsl, cur ^ 1, pb);
        }
        __syncthreads();
    }

#pragma unroll
    for (int mi = 0; mi < 2; mi++) {
        const int r0 = brow + wm + mi * 16 + g;
#pragma unroll
        for (int ni = 0; ni < 4; ni++) {
            const int c = bcol + wn + ni * 8 + 2 * tg;
            float b0 = 0.f, b1 = 0.f;
            if (bias) { b0 = bias[c]; b1 = bias[c + 1]; }
            float2 o0 = make_float2(acc[mi][ni][0] + b0, acc[mi][ni][1] + b1);
            float2 o1 = make_float2(acc[mi][ni][2] + b0, acc[mi][ni][3] + b1);
            *(float2*)(C + (size_t)r0 * N + c)       = o0;
            *(float2*)(C + (size_t)(r0 + 8) * N + c) = o1;
        }
    }
}

__global__ void __launch_bounds__(128)
gemm4t(GT t0, GT t1, GT t2, GT t3, int e0, int e1, int e2)
{
    __shared__ u32t sm[4][2][64][SSTR];   // As, Bs, Asl, Bsl
    const int bx = blockIdx.x;
    GT t; int local;
    if (bx < e0)      { t = t0; local = bx; }
    else if (bx < e1) { t = t1; local = bx - e0; }
    else if (bx < e2) { t = t2; local = bx - e1; }
    else              { t = t3; local = bx - e2; }
    const int tX = local % t.tilesX;
    const int tY = local / t.tilesX;
    if (t.prec3)
        tf32_body<true>(sm[0], sm[1], sm[2], sm[3], t.A, t.B, t.C, t.N, t.K, t.bias, tX, tY);
    else
        tf32_body<false>(sm[0], sm[1], sm[2], sm[3], t.A, t.B, t.C, t.N, t.K, t.bias, tX, tY);
}

// ---------------- transpose Wqp [512,320] -> WqpT [320,512] -----------------
__global__ __launch_bounds__(256)
void transpose_kernel(const float* __restrict__ src, float* __restrict__ dst)
{
    __shared__ float tile[32][33];
    const int bx = blockIdx.x;
    const int by = blockIdx.y;
    const int txx = threadIdx.x;
    const int tyy = threadIdx.y;
    const int x  = bx * 32 + txx;
    const int y0 = by * 32 + tyy;
#pragma unroll
    for (int i = 0; i < 32; i += 8)
        tile[tyy + i][txx] = src[(size_t)(y0 + i) * QDIM + x];
    __syncthreads();
    const int dx  = by * 32 + txx;
    const int dy0 = bx * 32 + tyy;
#pragma unroll
    for (int i = 0; i < 32; i += 8)
        dst[(size_t)(dy0 + i) * DDIM + dx] = tile[txx][tyy + i];
}

// ---------------- L2 normalize memory slots (keys & values) ----------------
__global__ __launch_bounds__(256)
void l2norm_kernel(const float* __restrict__ keys, const float* __restrict__ vals)
{
    __shared__ float sbuf[8];
    const int row = blockIdx.x;
    const float* src = (blockIdx.y == 0) ? keys : vals;
    float* dst = (blockIdx.y == 0) ? g_keysN : g_valsN;
    const int t = threadIdx.x;

    float2 v = *(const float2*)(src + (size_t)row * DDIM + t * 2);
    float ss = v.x * v.x + v.y * v.y;
#pragma unroll
    for (int off = 16; off; off >>= 1) ss += __shfl_xor_sync(0xffffffffu, ss, off);
    if ((t & 31) == 0) sbuf[t >> 5] = ss;
    __syncthreads();
    float tot = 0.f;
#pragma unroll
    for (int w = 0; w < 8; w++) tot += sbuf[w];
    float inv = 1.0f / sqrtf(tot + 1e-12f);
    float2 o = make_float2(v.x * inv, v.y * inv);
    *(float2*)(dst + (size_t)row * DDIM + t * 2) = o;
}

// ============================================================================
// Fused top-32 (exact 4-pass radix select) + gathered multi-head attention.
// ============================================================================
__device__ __forceinline__ u32t f2ord(float f) {
    u32t b = __float_as_uint(f);
    return (b & 0x80000000u) ? ~b : (b | 0x80000000u);
}

__global__ __launch_bounds__(256)
void topk_attn_kernel(const float* __restrict__ scores,
                      const float* __restrict__ qh,
                      float* __restrict__ ctx)
{
    __shared__ u32t  s_hist[256];
    __shared__ u32t  s_suf[257];
    __shared__ int   s_idx[KSEL];
    __shared__ int   s_tie[KSEL];
    __shared__ int   s_cnt[2];
    __shared__ int   s_T;
    __shared__ float s_q[DDIM];
    __shared__ float s_dot[NHEAD][KSEL];

    const int row = blockIdx.x;
    const int t = threadIdx.x;
    const int lane = t & 31;
    const int wrp = t >> 5;

    u32t u[4];
#pragma unroll
    for (int j = 0; j < 4; j++)
        u[j] = f2ord(scores[(size_t)row * SSLOTS + t + j * 256]);
    s_q[t]       = qh[(size_t)row * DDIM + t];
    s_q[t + 256] = qh[(size_t)row * DDIM + t + 256];
    if (t < 2) s_cnt[t] = 0;

    u32t prefix = 0;
    int  need   = KSEL;

#pragma unroll
    for (int b = 3; b >= 0; b--) {
        const int sh = b * 8;
        s_hist[t] = 0;
        __syncthreads();
#pragma unroll
        for (int j = 0; j < 4; j++) {
            bool in = (b == 3) || ((u[j] >> (sh + 8)) == prefix);
            if (in) atomicAdd(&s_hist[(u[j] >> sh) & 255u], 1u);
        }
        __syncthreads();
        {
            u32t v = s_hist[t];
#pragma unroll
            for (int off = 1; off < 32; off <<= 1) {
                u32t o = __shfl_down_sync(0xffffffffu, v, off);
                if (lane + off < 32) v += o;
            }
            __shared__ u32t wsum[8];
            if (lane == 0) wsum[wrp] = v;
            __syncthreads();
            u32t woff = 0;
#pragma unroll
            for (int w = 0; w < 8; w++) woff += (w > wrp) ? wsum[w] : 0u;
            s_suf[t] = v + woff;
            if (t == 0) s_suf[256] = 0;
        }
        __syncthreads();
        if (s_suf[t] >= (u32t)need && s_suf[t + 1] < (u32t)need) s_T = t;
        __syncthreads();
        const int T = s_T;
        need -= (int)s_suf[T + 1];
        prefix = (prefix << 8) | (u32t)T;
        __syncthreads();
    }
    const u32t V = prefix;

#pragma unroll
    for (int j = 0; j < 4; j++) {
        if (u[j] > V) {
            int p = atomicAdd(&s_cnt[0], 1);
            s_idx[p] = t + j * 256;
        } else if (u[j] == V) {
            int p = atomicAdd(&s_cnt[1], 1);
            if (p < KSEL) s_tie[p] = t + j * 256;
        }
    }
    __syncthreads();
    if (t == 0) {
        int nt = min(s_cnt[1], KSEL);
        int base = s_cnt[0];
        for (int r = 0; r < need; r++) {
            int best = 1 << 30, bj = -1;
            for (int j = 0; j < nt; j++)
                if (s_tie[j] < best) { best = s_tie[j]; bj = j; }
            s_idx[base + r] = best;
            s_tie[bj] = 1 << 30;
        }
    }
    __syncthreads();

    // ---- attention: warp = head; coalesced cooperative dots ----
    const int h  = wrp;
    const int g  = lane >> 4;
    const int gl = lane & 15;

    const int myidx = s_idx[lane];

    float4 qv = *(const float4*)&s_q[h * DHEAD + gl * 4];

#pragma unroll
    for (int i = 0; i < 16; i++) {
        const int slot = i * 2 + g;
        const int rowi = __shfl_sync(0xffffffffu, myidx, slot);
        float4 kv = *(const float4*)(g_Kp + (size_t)rowi * DDIM + h * DHEAD + gl * 4);
        float p = qv.x * kv.x + qv.y * kv.y + qv.z * kv.z + qv.w * kv.w;
        p += __shfl_xor_sync(0xffffffffu, p, 8);
        p += __shfl_xor_sync(0xffffffffu, p, 4);
        p += __shfl_xor_sync(0xffffffffu, p, 2);
        p += __shfl_xor_sync(0xffffffffu, p, 1);
        if (gl == 0) s_dot[h][slot] = p;
    }
    __syncwarp();

    float dot = s_dot[h][lane] * 0.125f;
    float m = dot;
#pragma unroll
    for (int off = 16; off; off >>= 1) m = fmaxf(m, __shfl_xor_sync(0xffffffffu, m, off));
    float e = expf(dot - m);
    float s = e;
#pragma unroll
    for (int off = 16; off; off >>= 1) s += __shfl_xor_sync(0xffffffffu, s, off);
    const float myw = e / s;

    {
        const int d2 = t * 2;
        float2 acc = make_float2(0.f, 0.f);
#pragma unroll 8
        for (int kk = 0; kk < KSEL; kk++) {
            const float wv = __shfl_sync(0xffffffffu, myw, kk);
            const int rk = __shfl_sync(0xffffffffu, myidx, kk);
            float2 v = *(const float2*)(g_Vp + (size_t)rk * DDIM + d2);
            acc.x = fmaf(wv, v.x, acc.x);
            acc.y = fmaf(wv, v.y, acc.y);
        }
        *(float2*)(ctx + (size_t)row * DDIM + d2) = acc;
    }
}

// ---------------- LayerNorm over D=512 -------------------------------------
__global__ __launch_bounds__(256)
void ln_kernel(const float* __restrict__ x, const float* __restrict__ g,
               const float* __restrict__ b, float* __restrict__ y)
{
    __shared__ float sbuf[8];
    __shared__ float sbuf2[8];
    const int row = blockIdx.x;
    const int t = threadIdx.x;

    float2 v = *(const float2*)(x + (size_t)row * DDIM + t * 2);
    float s = v.x + v.y;
#pragma unroll
    for (int off = 16; off; off >>= 1) s += __shfl_xor_sync(0xffffffffu, s, off);
    if ((t & 31) == 0) sbuf[t >> 5] = s;
    __syncthreads();
    float tot = 0.f;
#pragma unroll
    for (int w = 0; w < 8; w++) tot += sbuf[w];
    float mu = tot * (1.0f / DDIM);

    float dx = v.x - mu, dy = v.y - mu;
    float ss = dx * dx + dy * dy;
#pragma unroll
    for (int off = 16; off; off >>= 1) ss += __shfl_xor_sync(0xffffffffu, ss, off);
    if ((t & 31) == 0) sbuf2[t >> 5] = ss;
    __syncthreads();
    float vs = 0.f;
#pragma unroll
    for (int w = 0; w < 8; w++) vs += sbuf2[w];
    float rstd = 1.0f / sqrtf(vs * (1.0f / DDIM) + 1e-5f);

    float2 o;
    o.x = dx * rstd * g[t * 2 + 0] + b[t * 2 + 0];
    o.y = dy * rstd * g[t * 2 + 1] + b[t * 2 + 1];
    *(float2*)(y + (size_t)row * DDIM + t * 2) = o;
}

// ---------------- launch ----------------------------------------------------
extern "C" void kernel_launch(void* const* d_in, const int* in_sizes, int n_in,
                              void* d_out, int out_size)
{
    const float* query = (const float*)d_in[0];
    const float* Wqp   = (const float*)d_in[1];
    const float* mkeys = (const float*)d_in[2];
    const float* mvals = (const float*)d_in[3];
    const float* Wq    = (const float*)d_in[4];
    const float* Wk    = (const float*)d_in[5];
    const float* Wv    = (const float*)d_in[6];
    const float* Wo    = (const float*)d_in[7];
    const float* ln_g  = (const float*)d_in[8];
    const float* ln_b  = (const float*)d_in[9];
    const float* Wout  = (const float*)d_in[10];
    const float* bout  = (const float*)d_in[11];
    float* out = (float*)d_out;

    float *keysN, *valsN, *Kp, *Vp, *qh, *scores, *ctx, *ctxo, *normed;
    float *WqpT, *Wqq, *M;
    cudaGetSymbolAddress((void**)&keysN,  g_keysN);
    cudaGetSymbolAddress((void**)&valsN,  g_valsN);
    cudaGetSymbolAddress((void**)&Kp,     g_Kp);
    cudaGetSymbolAddress((void**)&Vp,     g_Vp);
    cudaGetSymbolAddress((void**)&qh,     g_qh);
    cudaGetSymbolAddress((void**)&scores, g_scores);
    cudaGetSymbolAddress((void**)&ctx,    g_ctx);
    cudaGetSymbolAddress((void**)&ctxo,   g_ctxo);
    cudaGetSymbolAddress((void**)&normed, g_normed);
    cudaGetSymbolAddress((void**)&WqpT,   g_WqpT);
    cudaGetSymbolAddress((void**)&Wqq,    g_Wqq);
    cudaGetSymbolAddress((void**)&M,      g_M);

    // 1) normalize slot tables; transpose Wqp
    l2norm_kernel<<<dim3(SSLOTS, 2), 256>>>(mkeys, mvals);
    transpose_kernel<<<dim3(QDIM / 32, DDIM / 32), dim3(32, 8)>>>(Wqp, WqpT);

    // 2) fp32 precomputes: M = keysN @ WqpT^T [1024,320]; Wqq = Wq @ WqpT^T
    {
        GT tm   = {keysN, WqpT, M,   QDIM, DDIM, nullptr, QDIM / BN, 0};
        GT twqq = {Wq,    WqpT, Wqq, QDIM, DDIM, nullptr, QDIM / BN, 0};
        GT dmy  = twqq;
        gemm4<<<80 + 40, 64>>>(tm, twqq, dmy, dmy, 80, 120, 120);
    }

    // 3) ONE tensor-core launch (1792 blocks):
    //    scores = query @ M^T  [4096,1024] K=320  3xTF32 (fp32-class, top-k safe)
    //    qh     = query @ Wqq^T [4096,512] K=320  tf32
    //    Kp     = keysN @ Wk^T  [1024,512] K=512  tf32
    //    Vp     = valsN @ Wv^T  [1024,512] K=512  tf32
    {
        GT tsc = {query, M,   scores, SSLOTS, QDIM, nullptr, SSLOTS / 64, 1};
        GT tqh = {query, Wqq, qh,     DDIM,   QDIM, nullptr, DDIM / 64,   0};
        GT tkp = {keysN, Wk,  Kp,     DDIM,   DDIM, nullptr, DDIM / 64,   0};
        GT tvp = {valsN, Wv,  Vp,     DDIM,   DDIM, nullptr, DDIM / 64,   0};
        gemm4t<<<1024 + 512 + 128 + 128, 128>>>(tsc, tqh, tkp, tvp, 1024, 1536, 1664);
    }

    // 4) fused radix-select top-32 + attention -> ctx [4096,512]
    topk_attn_kernel<<<TOKS, 256>>>(scores, qh, ctx);

    // 5) tf32: ctxo = ctx @ Wo^T (512 tiles)
    {
        GT two = {ctx, Wo, ctxo, DDIM, DDIM, nullptr, DDIM / 64, 0};
        gemm4t<<<512, 128>>>(two, two, two, two, 512, 512, 512);
    }

    // 6) LayerNorm
    ln_kernel<<<TOKS, 256>>>(ctxo, ln_g, ln_b, normed);

    // 7) tf32: out = normed @ Wout^T + bout [4096,320] (320 tiles)
    {
        GT tout = {normed, Wout, out, QDIM, DDIM, bout, QDIM / 64, 0};
        gemm4t<<<320, 128>>>(tout, tout, tout, tout, 320, 320, 320);
    }
}

// round 9
// speedup vs baseline: 2.7755x; 1.0934x over previous
#include <cuda_runtime.h>
#include <math.h>

// Problem constants
#define TOKS   4096   // B*N
#define DDIM   512
#define SSLOTS 1024
#define QDIM   320
#define KSEL   32
#define NHEAD  8
#define DHEAD  64

typedef unsigned long long u64t;
typedef unsigned int u32t;

// ---------------- scratch (device globals; no allocation allowed) ----------
__device__ float g_keysN[SSLOTS * DDIM];
__device__ float g_valsN[SSLOTS * DDIM];
__device__ float g_Kp[SSLOTS * DDIM];
__device__ float g_Vp[SSLOTS * DDIM];
__device__ float g_qh[TOKS * DDIM];
__device__ float g_scores[TOKS * SSLOTS];
__device__ float g_ctx[TOKS * DDIM];
__device__ float g_ctxo[TOKS * DDIM];
__device__ float g_normed[TOKS * DDIM];
__device__ float g_WqpT[QDIM * DDIM];   // Wqp transposed [320,512]
__device__ float g_Wqq[DDIM * QDIM];    // Wq @ Wqp       [512,320]
__device__ float g_M[SSLOTS * QDIM];    // keysN @ Wqp    [1024,320]

struct GT {
    const float* A;
    const float* B;
    float*       C;
    int N, K;
    const float* bias;
    int tilesX;   // N / 64
    int prec3;    // 1 = 3xTF32 split-precision (fp32-class accuracy)
};

// ============================================================================
// tf32 tensor-core GEMM NT: 64x64 tile, 128 threads (2x2 warp grid of 32x32),
// mma.sync.m16n8k8, ldmatrix fragment loads. P3=true: 3xTF32 split scheme
// (hi*hi + hi*lo + lo*hi) = fp32-class accuracy at tensor-core rate.
// ============================================================================
#define TBK 16
#define SSTR 20   // smem row stride (words); rows 16B-aligned, phase-conflict-free

__device__ __forceinline__ u32t cvt_tf32(float x) {
    u32t r;
    asm("cvt.rna.tf32.f32 %0, %1;" : "=r"(r) : "f"(x));
    return r;
}
__device__ __forceinline__ u32t smem_u32(const void* p) {
    return (u32t)__cvta_generic_to_shared(p);
}

#define MMA_TF32(d, a0, a1, a2, a3, b0, b1)                                   \
    asm volatile("mma.sync.aligned.m16n8k8.row.col.f32.tf32.tf32.f32 "       \
                 "{%0,%1,%2,%3}, {%4,%5,%6,%7}, {%8,%9}, {%0,%1,%2,%3};"     \
                 : "+f"(d[0]), "+f"(d[1]), "+f"(d[2]), "+f"(d[3])            \
                 : "r"(a0), "r"(a1), "r"(a2), "r"(a3), "r"(b0), "r"(b1))

#define LDSM4(r, addr)                                                        \
    asm volatile("ldmatrix.sync.aligned.m8n8.x4.shared.b16 {%0,%1,%2,%3}, [%4];" \
                 : "=r"(r[0]), "=r"(r[1]), "=r"(r[2]), "=r"(r[3]) : "r"(addr))

template<bool P3>
__device__ __forceinline__ void tf32_body(
    u32t (*As)[64][SSTR], u32t (*Bs)[64][SSTR],
    u32t (*Asl)[64][SSTR], u32t (*Bsl)[64][SSTR],
    const float* __restrict__ A, const float* __restrict__ B,
    float* __restrict__ C, int N, int K, const float* __restrict__ bias,
    int tileX, int tileY)
{
    const int tid  = threadIdx.x;
    const int warp = tid >> 5;
    const int lane = tid & 31;
    const int g    = lane >> 2;
    const int tg   = lane & 3;
    const int wm   = (warp >> 1) * 32;
    const int wn   = (warp & 1) * 32;
    const int brow = tileY * 64;
    const int bcol = tileX * 64;

    // ldmatrix per-lane source rows:
    //  A (x4 covers a0..a3 of one 16-row m-frag): groups of 8 lanes supply
    //  rows for matrices {rows g.., rows g+8.., same at kcol+4}.
    const int lrow8   = lane & 7;
    const int aRowOff = lrow8 + ((lane >> 3) & 1) * 8;  // 0..15 within m-frag
    const int aKsel   = (lane >> 4) * 4;                // 0 | 4 (kcol half)
    const int bRow    = wn + (lane >> 3) * 8 + lrow8;   // b matrices = ni 0..3

    float4 pa[2], pb[2];

    auto loadA = [&](int k0) {
#pragma unroll
        for (int i = 0; i < 2; i++) {
            int slot = tid + i * 128;
            int row = slot >> 2, kq = slot & 3;
            pa[i] = *(const float4*)(A + (size_t)(brow + row) * K + k0 + kq * 4);
        }
    };
    auto loadB = [&](int k0) {
#pragma unroll
        for (int i = 0; i < 2; i++) {
            int slot = tid + i * 128;
            int row = slot >> 2, kq = slot & 3;
            pb[i] = *(const float4*)(B + (size_t)(bcol + row) * K + k0 + kq * 4);
        }
    };
    auto split_store = [&](u32t (*hi)[64][SSTR], u32t (*lo)[64][SSTR],
                           int buf, float4* p) {
#pragma unroll
        for (int i = 0; i < 2; i++) {
            int slot = tid + i * 128;
            int row = slot >> 2, kq = slot & 3;
            float v[4] = {p[i].x, p[i].y, p[i].z, p[i].w};
            uint4 qh_, ql_;
            u32t* qhp = (u32t*)&qh_;
            u32t* qlp = (u32t*)&ql_;
#pragma unroll
            for (int c = 0; c < 4; c++) {
                u32t h = cvt_tf32(v[c]);
                qhp[c] = h;
                if (P3) qlp[c] = cvt_tf32(v[c] - __uint_as_float(h));
            }
            *(uint4*)&hi[buf][row][kq * 4] = qh_;
            if (P3) *(uint4*)&lo[buf][row][kq * 4] = ql_;
        }
    };

    float acc[2][4][4];
#pragma unroll
    for (int mi = 0; mi < 2; mi++)
#pragma unroll
        for (int ni = 0; ni < 4; ni++)
#pragma unroll
            for (int r = 0; r < 4; r++) acc[mi][ni][r] = 0.f;

    const int ntiles = K / TBK;
    loadA(0); loadB(0);
    split_store(As, Asl, 0, pa);
    split_store(Bs, Bsl, 0, pb);
    __syncthreads();

    for (int t = 0; t < ntiles; t++) {
        const int cur = t & 1;
        const bool more = (t + 1 < ntiles);
        if (more) { loadA((t + 1) * TBK); loadB((t + 1) * TBK); }

#pragma unroll
        for (int ks = 0; ks < 2; ks++) {
            const int kb = ks * 8;
            u32t a[2][4], bb0[4], bb1[4];
            u32t al[2][4], bl0[4], bl1[4];
#pragma unroll
            for (int mi = 0; mi < 2; mi++) {
                u32t addr = smem_u32(&As[cur][wm + mi * 16 + aRowOff][kb + aKsel]);
                LDSM4(a[mi], addr);
                if (P3) {
                    u32t addrl = smem_u32(&Asl[cur][wm + mi * 16 + aRowOff][kb + aKsel]);
                    LDSM4(al[mi], addrl);
                }
            }
            {
                u32t b0a = smem_u32(&Bs[cur][bRow][kb]);
                u32t b1a = smem_u32(&Bs[cur][bRow][kb + 4]);
                LDSM4(bb0, b0a);
                LDSM4(bb1, b1a);
                if (P3) {
                    u32t c0a = smem_u32(&Bsl[cur][bRow][kb]);
                    u32t c1a = smem_u32(&Bsl[cur][bRow][kb + 4]);
                    LDSM4(bl0, c0a);
                    LDSM4(bl1, c1a);
                }
            }
#pragma unroll
            for (int mi = 0; mi < 2; mi++)
#pragma unroll
                for (int ni = 0; ni < 4; ni++) {
                    if (P3) {
                        MMA_TF32(acc[mi][ni], a[mi][0], a[mi][1], a[mi][2], a[mi][3],
                                 bl0[ni], bl1[ni]);                       // hi*lo
                        MMA_TF32(acc[mi][ni], al[mi][0], al[mi][1], al[mi][2], al[mi][3],
                                 bb0[ni], bb1[ni]);                       // lo*hi
                    }
                    MMA_TF32(acc[mi][ni], a[mi][0], a[mi][1], a[mi][2], a[mi][3],
                             bb0[ni], bb1[ni]);                           // hi*hi
                }
        }
        if (more) {
            split_store(As, Asl, cur ^ 1, pa);
            split_store(Bs, Bsl, cur ^ 1, pb);
        }
        __syncthreads();
    }

#pragma unroll
    for (int mi = 0; mi < 2; mi++) {
        const int r0 = brow + wm + mi * 16 + g;
#pragma unroll
        for (int ni = 0; ni < 4; ni++) {
            const int c = bcol + wn + ni * 8 + 2 * tg;
            float b0 = 0.f, b1 = 0.f;
            if (bias) { b0 = bias[c]; b1 = bias[c + 1]; }
            float2 o0 = make_float2(acc[mi][ni][0] + b0, acc[mi][ni][1] + b1);
            float2 o1 = make_float2(acc[mi][ni][2] + b0, acc[mi][ni][3] + b1);
            *(float2*)(C + (size_t)r0 * N + c)       = o0;
            *(float2*)(C + (size_t)(r0 + 8) * N + c) = o1;
        }
    }
}

__global__ void __launch_bounds__(128)
gemm4t(GT t0, GT t1, GT t2, GT t3, int e0, int e1, int e2)
{
    __shared__ u32t sm[4][2][64][SSTR];   // As, Bs, Asl, Bsl
    const int bx = blockIdx.x;
    GT t; int local;
    if (bx < e0)      { t = t0; local = bx; }
    else if (bx < e1) { t = t1; local = bx - e0; }
    else if (bx < e2) { t = t2; local = bx - e1; }
    else              { t = t3; local = bx - e2; }
    const int tX = local % t.tilesX;
    const int tY = local / t.tilesX;
    if (t.prec3)
        tf32_body<true>(sm[0], sm[1], sm[2], sm[3], t.A, t.B, t.C, t.N, t.K, t.bias, tX, tY);
    else
        tf32_body<false>(sm[0], sm[1], sm[2], sm[3], t.A, t.B, t.C, t.N, t.K, t.bias, tX, tY);
}

// ---------------- transpose Wqp [512,320] -> WqpT [320,512] -----------------
__global__ __launch_bounds__(256)
void transpose_kernel(const float* __restrict__ src, float* __restrict__ dst)
{
    __shared__ float tile[32][33];
    const int bx = blockIdx.x;
    const int by = blockIdx.y;
    const int txx = threadIdx.x;
    const int tyy = threadIdx.y;
    const int x  = bx * 32 + txx;
    const int y0 = by * 32 + tyy;
#pragma unroll
    for (int i = 0; i < 32; i += 8)
        tile[tyy + i][txx] = src[(size_t)(y0 + i) * QDIM + x];
    __syncthreads();
    const int dx  = by * 32 + txx;
    const int dy0 = bx * 32 + tyy;
#pragma unroll
    for (int i = 0; i < 32; i += 8)
        dst[(size_t)(dy0 + i) * DDIM + dx] = tile[txx][tyy + i];
}

// ---------------- L2 normalize memory slots (keys & values) ----------------
__global__ __launch_bounds__(256)
void l2norm_kernel(const float* __restrict__ keys, const float* __restrict__ vals)
{
    __shared__ float sbuf[8];
    const int row = blockIdx.x;
    const float* src = (blockIdx.y == 0) ? keys : vals;
    float* dst = (blockIdx.y == 0) ? g_keysN : g_valsN;
    const int t = threadIdx.x;

    float2 v = *(const float2*)(src + (size_t)row * DDIM + t * 2);
    float ss = v.x * v.x + v.y * v.y;
#pragma unroll
    for (int off = 16; off; off >>= 1) ss += __shfl_xor_sync(0xffffffffu, ss, off);
    if ((t & 31) == 0) sbuf[t >> 5] = ss;
    __syncthreads();
    float tot = 0.f;
#pragma unroll
    for (int w = 0; w < 8; w++) tot += sbuf[w];
    float inv = 1.0f / sqrtf(tot + 1e-12f);
    float2 o = make_float2(v.x * inv, v.y * inv);
    *(float2*)(dst + (size_t)row * DDIM + t * 2) = o;
}

// ============================================================================
// Fused top-32 (exact 4-pass radix select) + gathered multi-head attention.
// ============================================================================
__device__ __forceinline__ u32t f2ord(float f) {
    u32t b = __float_as_uint(f);
    return (b & 0x80000000u) ? ~b : (b | 0x80000000u);
}

__global__ __launch_bounds__(256)
void topk_attn_kernel(const float* __restrict__ scores,
                      const float* __restrict__ qh,
                      float* __restrict__ ctx)
{
    __shared__ u32t  s_hist[256];
    __shared__ u32t  s_suf[257];
    __shared__ int   s_idx[KSEL];
    __shared__ int   s_tie[KSEL];
    __shared__ int   s_cnt[2];
    __shared__ int   s_T;
    __shared__ float s_q[DDIM];
    __shared__ float s_dot[NHEAD][KSEL];

    const int row = blockIdx.x;
    const int t = threadIdx.x;
    const int lane = t & 31;
    const int wrp = t >> 5;

    u32t u[4];
#pragma unroll
    for (int j = 0; j < 4; j++)
        u[j] = f2ord(scores[(size_t)row * SSLOTS + t + j * 256]);
    s_q[t]       = qh[(size_t)row * DDIM + t];
    s_q[t + 256] = qh[(size_t)row * DDIM + t + 256];
    if (t < 2) s_cnt[t] = 0;

    u32t prefix = 0;
    int  need   = KSEL;

#pragma unroll
    for (int b = 3; b >= 0; b--) {
        const int sh = b * 8;
        s_hist[t] = 0;
        __syncthreads();
#pragma unroll
        for (int j = 0; j < 4; j++) {
            bool in = (b == 3) || ((u[j] >> (sh + 8)) == prefix);
            if (in) atomicAdd(&s_hist[(u[j] >> sh) & 255u], 1u);
        }
        __syncthreads();
        {
            u32t v = s_hist[t];
#pragma unroll
            for (int off = 1; off < 32; off <<= 1) {
                u32t o = __shfl_down_sync(0xffffffffu, v, off);
                if (lane + off < 32) v += o;
            }
            __shared__ u32t wsum[8];
            if (lane == 0) wsum[wrp] = v;
            __syncthreads();
            u32t woff = 0;
#pragma unroll
            for (int w = 0; w < 8; w++) woff += (w > wrp) ? wsum[w] : 0u;
            s_suf[t] = v + woff;
            if (t == 0) s_suf[256] = 0;
        }
        __syncthreads();
        if (s_suf[t] >= (u32t)need && s_suf[t + 1] < (u32t)need) s_T = t;
        __syncthreads();
        const int T = s_T;
        need -= (int)s_suf[T + 1];
        prefix = (prefix << 8) | (u32t)T;
        __syncthreads();
    }
    const u32t V = prefix;

#pragma unroll
    for (int j = 0; j < 4; j++) {
        if (u[j] > V) {
            int p = atomicAdd(&s_cnt[0], 1);
            s_idx[p] = t + j * 256;
        } else if (u[j] == V) {
            int p = atomicAdd(&s_cnt[1], 1);
            if (p < KSEL) s_tie[p] = t + j * 256;
        }
    }
    __syncthreads();
    if (t == 0) {
        int nt = min(s_cnt[1], KSEL);
        int base = s_cnt[0];
        for (int r = 0; r < need; r++) {
            int best = 1 << 30, bj = -1;
            for (int j = 0; j < nt; j++)
                if (s_tie[j] < best) { best = s_tie[j]; bj = j; }
            s_idx[base + r] = best;
            s_tie[bj] = 1 << 30;
        }
    }
    __syncthreads();

    // ---- attention: warp = head; coalesced cooperative dots ----
    const int h  = wrp;
    const int g  = lane >> 4;
    const int gl = lane & 15;

    const int myidx = s_idx[lane];

    float4 qv = *(const float4*)&s_q[h * DHEAD + gl * 4];

#pragma unroll
    for (int i = 0; i < 16; i++) {
        const int slot = i * 2 + g;
        const int rowi = __shfl_sync(0xffffffffu, myidx, slot);
        float4 kv = *(const float4*)(g_Kp + (size_t)rowi * DDIM + h * DHEAD + gl * 4);
        float p = qv.x * kv.x + qv.y * kv.y + qv.z * kv.z + qv.w * kv.w;
        p += __shfl_xor_sync(0xffffffffu, p, 8);
        p += __shfl_xor_sync(0xffffffffu, p, 4);
        p += __shfl_xor_sync(0xffffffffu, p, 2);
        p += __shfl_xor_sync(0xffffffffu, p, 1);
        if (gl == 0) s_dot[h][slot] = p;
    }
    __syncwarp();

    float dot = s_dot[h][lane] * 0.125f;
    float m = dot;
#pragma unroll
    for (int off = 16; off; off >>= 1) m = fmaxf(m, __shfl_xor_sync(0xffffffffu, m, off));
    float e = expf(dot - m);
    float s = e;
#pragma unroll
    for (int off = 16; off; off >>= 1) s += __shfl_xor_sync(0xffffffffu, s, off);
    const float myw = e / s;

    {
        const int d2 = t * 2;
        float2 acc = make_float2(0.f, 0.f);
#pragma unroll 8
        for (int kk = 0; kk < KSEL; kk++) {
            const float wv = __shfl_sync(0xffffffffu, myw, kk);
            const int rk = __shfl_sync(0xffffffffu, myidx, kk);
            float2 v = *(const float2*)(g_Vp + (size_t)rk * DDIM + d2);
            acc.x = fmaf(wv, v.x, acc.x);
            acc.y = fmaf(wv, v.y, acc.y);
        }
        *(float2*)(ctx + (size_t)row * DDIM + d2) = acc;
    }
}

// ---------------- LayerNorm over D=512 -------------------------------------
__global__ __launch_bounds__(256)
void ln_kernel(const float* __restrict__ x, const float* __restrict__ g,
               const float* __restrict__ b, float* __restrict__ y)
{
    __shared__ float sbuf[8];
    __shared__ float sbuf2[8];
    const int row = blockIdx.x;
    const int t = threadIdx.x;

    float2 v = *(const float2*)(x + (size_t)row * DDIM + t * 2);
    float s = v.x + v.y;
#pragma unroll
    for (int off = 16; off; off >>= 1) s += __shfl_xor_sync(0xffffffffu, s, off);
    if ((t & 31) == 0) sbuf[t >> 5] = s;
    __syncthreads();
    float tot = 0.f;
#pragma unroll
    for (int w = 0; w < 8; w++) tot += sbuf[w];
    float mu = tot * (1.0f / DDIM);

    float dx = v.x - mu, dy = v.y - mu;
    float ss = dx * dx + dy * dy;
#pragma unroll
    for (int off = 16; off; off >>= 1) ss += __shfl_xor_sync(0xffffffffu, ss, off);
    if ((t & 31) == 0) sbuf2[t >> 5] = ss;
    __syncthreads();
    float vs = 0.f;
#pragma unroll
    for (int w = 0; w < 8; w++) vs += sbuf2[w];
    float rstd = 1.0f / sqrtf(vs * (1.0f / DDIM) + 1e-5f);

    float2 o;
    o.x = dx * rstd * g[t * 2 + 0] + b[t * 2 + 0];
    o.y = dy * rstd * g[t * 2 + 1] + b[t * 2 + 1];
    *(float2*)(y + (size_t)row * DDIM + t * 2) = o;
}

// ---------------- launch ----------------------------------------------------
extern "C" void kernel_launch(void* const* d_in, const int* in_sizes, int n_in,
                              void* d_out, int out_size)
{
    const float* query = (const float*)d_in[0];
    const float* Wqp   = (const float*)d_in[1];
    const float* mkeys = (const float*)d_in[2];
    const float* mvals = (const float*)d_in[3];
    const float* Wq    = (const float*)d_in[4];
    const float* Wk    = (const float*)d_in[5];
    const float* Wv    = (const float*)d_in[6];
    const float* Wo    = (const float*)d_in[7];
    const float* ln_g  = (const float*)d_in[8];
    const float* ln_b  = (const float*)d_in[9];
    const float* Wout  = (const float*)d_in[10];
    const float* bout  = (const float*)d_in[11];
    float* out = (float*)d_out;

    float *keysN, *valsN, *Kp, *Vp, *qh, *scores, *ctx, *ctxo, *normed;
    float *WqpT, *Wqq, *M;
    cudaGetSymbolAddress((void**)&keysN,  g_keysN);
    cudaGetSymbolAddress((void**)&valsN,  g_valsN);
    cudaGetSymbolAddress((void**)&Kp,     g_Kp);
    cudaGetSymbolAddress((void**)&Vp,     g_Vp);
    cudaGetSymbolAddress((void**)&qh,     g_qh);
    cudaGetSymbolAddress((void**)&scores, g_scores);
    cudaGetSymbolAddress((void**)&ctx,    g_ctx);
    cudaGetSymbolAddress((void**)&ctxo,   g_ctxo);
    cudaGetSymbolAddress((void**)&normed, g_normed);
    cudaGetSymbolAddress((void**)&WqpT,   g_WqpT);
    cudaGetSymbolAddress((void**)&Wqq,    g_Wqq);
    cudaGetSymbolAddress((void**)&M,      g_M);

    // 1) normalize slot tables; transpose Wqp
    l2norm_kernel<<<dim3(SSLOTS, 2), 256>>>(mkeys, mvals);
    transpose_kernel<<<dim3(QDIM / 32, DDIM / 32), dim3(32, 8)>>>(Wqp, WqpT);

    // 2) precomputes on tensor cores:
    //    M = keysN @ WqpT^T [1024,320] K=512  3xTF32 (feeds top-k scores)
    //    Wqq = Wq @ WqpT^T  [512,320]  K=512  tf32
    {
        GT tm   = {keysN, WqpT, M,   QDIM, DDIM, nullptr, QDIM / 64, 1};
        GT twqq = {Wq,    WqpT, Wqq, QDIM, DDIM, nullptr, QDIM / 64, 0};
        GT dmy  = twqq;
        gemm4t<<<80 + 40, 128>>>(tm, twqq, dmy, dmy, 80, 120, 120);
    }

    // 3) ONE tensor-core launch (1792 blocks):
    //    scores = query @ M^T  [4096,1024] K=320  3xTF32 (fp32-class, top-k safe)
    //    qh     = query @ Wqq^T [4096,512] K=320  tf32
    //    Kp     = keysN @ Wk^T  [1024,512] K=512  tf32
    //    Vp     = valsN @ Wv^T  [1024,512] K=512  tf32
    {
        GT tsc = {query, M,   scores, SSLOTS, QDIM, nullptr, SSLOTS / 64, 1};
        GT tqh = {query, Wqq, qh,     DDIM,   QDIM, nullptr, DDIM / 64,   0};
        GT tkp = {keysN, Wk,  Kp,     DDIM,   DDIM, nullptr, DDIM / 64,   0};
        GT tvp = {valsN, Wv,  Vp,     DDIM,   DDIM, nullptr, DDIM / 64,   0};
        gemm4t<<<1024 + 512 + 128 + 128, 128>>>(tsc, tqh, tkp, tvp, 1024, 1536, 1664);
    }

    // 4) fused radix-select top-32 + attention -> ctx [4096,512]
    topk_attn_kernel<<<TOKS, 256>>>(scores, qh, ctx);

    // 5) tf32: ctxo = ctx @ Wo^T (512 tiles)
    {
        GT two = {ctx, Wo, ctxo, DDIM, DDIM, nullptr, DDIM / 64, 0};
        gemm4t<<<512, 128>>>(two, two, two, two, 512, 512, 512);
    }

    // 6) LayerNorm
    ln_kernel<<<TOKS, 256>>>(ctxo, ln_g, ln_b, normed);

    // 7) tf32: out = normed @ Wout^T + bout [4096,320] (320 tiles)
    {
        GT tout = {normed, Wout, out, QDIM, DDIM, bout, QDIM / 64, 0};
        gemm4t<<<320, 128>>>(tout, tout, tout, tout, 320, 320, 320);
    }
}